// round 3
// baseline (speedup 1.0000x reference)
#include <cuda_runtime.h>

// MinimalRNN: 3-layer tanh RNN, S=256, B=256, H=1024.
// Persistent cooperative kernel, skewed layer pipeline (layer l computes
// timestep t = s - l at global step s), one grid barrier per global step.
// fp32 compute via packed fma.rn.f32x2 (2 MACs / instruction).

#define S_LEN   256
#define BATCH   256
#define HID     1024
#define NLAYER  3
#define NT      16                 // output columns per CTA
#define TPL     (HID / NT)         // 64 tiles per layer
#define NCTA    (NLAYER * TPL)     // 192
#define NTHREADS 256
#define KC      32                 // K-chunk staged in SMEM
#define ASTR    (KC + 4)           // 36 floats: A-tile row stride (pad)
#define WSTR    (NT + 4)           // 20 floats: W-tile row stride (pad)

#define Y_ELEMS ((size_t)S_LEN * BATCH * HID)

// Double-buffered hidden state: parity = global step s & 1.
__device__ __align__(16) float g_hbuf[2][NLAYER][BATCH][HID];
__device__ unsigned g_count = 0;
__device__ unsigned g_gen   = 0;

__device__ __forceinline__ unsigned ld_acq(const unsigned* p) {
    unsigned v;
    asm volatile("ld.acquire.gpu.global.u32 %0, [%1];" : "=r"(v) : "l"(p) : "memory");
    return v;
}

__device__ __forceinline__ void grid_barrier() {
    __syncthreads();
    if (threadIdx.x == 0) {
        __threadfence();
        unsigned gen = ld_acq(&g_gen);     // read BEFORE arriving
        __threadfence();
        unsigned ticket = atomicAdd(&g_count, 1u);
        if (ticket == NCTA - 1) {
            atomicExch(&g_count, 0u);      // reset before release
            __threadfence();
            atomicAdd(&g_gen, 1u);
        } else {
            while (ld_acq(&g_gen) == gen) { __nanosleep(64); }
        }
        __threadfence();
    }
    __syncthreads();
}

// ---- packed f32x2 helpers ----
__device__ __forceinline__ void ffma2(unsigned long long& d,
                                      unsigned long long a,
                                      unsigned long long b) {
    asm volatile("fma.rn.f32x2 %0, %1, %2, %0;" : "+l"(d) : "l"(a), "l"(b));
}
__device__ __forceinline__ unsigned long long splat2(float v) {
    unsigned long long r;
    asm("mov.b64 %0, {%1, %1};" : "=l"(r) : "f"(v));
    return r;
}
__device__ __forceinline__ unsigned long long pack2(float a, float b) {
    unsigned long long r;
    asm("mov.b64 %0, {%1, %2};" : "=l"(r) : "f"(a), "f"(b));
    return r;
}
__device__ __forceinline__ float2 unpack2(unsigned long long v) {
    float2 f;
    asm("mov.b64 {%0, %1}, %2;" : "=f"(f.x), "=f"(f.y) : "l"(v));
    return f;
}

// Accumulate acc[4 rows][2 col-pairs] += A[256 x 1024] * W[n0..n0+15][1024]^T
// A rows r = ty + 64*ri, cols c = n0 + tx*4 + {0..3}.
__device__ __forceinline__ void gemm_acc(
    const float* __restrict__ A,   // [BATCH][HID] activations (L1-bypassed reads)
    const float* __restrict__ W,   // [HID][HID] weight matrix (row-major, row = out col)
    int n0, int tid, int ty, int tx,
    unsigned long long acc[4][2],
    float At[BATCH][ASTR], float Wt[KC][WSTR])
{
    const int arow = tid >> 3;     // 0..31
    const int aq   = tid & 7;      // 0..7 : float4 index within KC
    const int wc   = tid & 15;     // weight col within tile
    const int wq   = tid >> 4;     // 0..7 when tid < 128

    for (int kc = 0; kc < HID; kc += KC) {
        // stage A chunk [256 x KC]: 8 lanes cover one row's 128B -> coalesced
        #pragma unroll
        for (int it = 0; it < 8; it++) {
            int row = arow + 32 * it;
            float4 v = __ldcg((const float4*)(A + (size_t)row * HID + kc + aq * 4));
            *(float4*)&At[row][aq * 4] = v;
        }
        // stage W chunk transposed: Wt[kk][c] = W[n0+c][kc+kk]
        if (tid < 128) {
            float4 wv = __ldg((const float4*)(W + (size_t)(n0 + wc) * HID + kc + wq * 4));
            Wt[wq * 4 + 0][wc] = wv.x;
            Wt[wq * 4 + 1][wc] = wv.y;
            Wt[wq * 4 + 2][wc] = wv.z;
            Wt[wq * 4 + 3][wc] = wv.w;
        }
        __syncthreads();

        #pragma unroll
        for (int k4 = 0; k4 < KC; k4 += 4) {
            ulonglong2 wp[4];                     // wp[j] = W cols (c0,c1),(c2,c3) at k4+j
            #pragma unroll
            for (int j = 0; j < 4; j++)
                wp[j] = *(const ulonglong2*)&Wt[k4 + j][tx * 4];
            float4 av[4];                         // av[ri] = A[row_ri][k4..k4+3]
            #pragma unroll
            for (int ri = 0; ri < 4; ri++)
                av[ri] = *(const float4*)&At[ty + 64 * ri][k4];
            #pragma unroll
            for (int j = 0; j < 4; j++) {
                #pragma unroll
                for (int ri = 0; ri < 4; ri++) {
                    float a = ((const float*)&av[ri])[j];
                    unsigned long long as = splat2(a);
                    ffma2(acc[ri][0], as, wp[j].x);
                    ffma2(acc[ri][1], as, wp[j].y);
                }
            }
        }
        __syncthreads();
    }
}

extern "C" __global__ void __launch_bounds__(NTHREADS, 2)
rnn_persistent(const float* __restrict__ x,   // [S][B][H]
               const float* __restrict__ h0,  // [L][B][H]
               const float* __restrict__ Wih, // [L][H][H]
               const float* __restrict__ Whh, // [L][H][H]
               const float* __restrict__ bih, // [L][H]
               const float* __restrict__ bhh, // [L][H]
               float* __restrict__ out)       // [S*B*H + L*B*H]
{
    __shared__ float At[BATCH][ASTR];
    __shared__ float Wt[KC][WSTR];

    const int tid = threadIdx.x;
    const int ty  = tid >> 2;      // 0..63 : batch-row group
    const int tx  = tid & 3;       // 0..3  : col group (4 cols each)
    const int l   = blockIdx.x / TPL;
    const int n0  = (blockIdx.x % TPL) * NT;

    const float* Wl_ih = Wih + (size_t)l * HID * HID;
    const float* Wl_hh = Whh + (size_t)l * HID * HID;

    float bias[4];
    #pragma unroll
    for (int j = 0; j < 4; j++) {
        int c = n0 + tx * 4 + j;
        bias[j] = __ldg(&bih[l * HID + c]) + __ldg(&bhh[l * HID + c]);
    }

    for (int s = 0; s < S_LEN + NLAYER - 1; s++) {
        if (s > 0) grid_barrier();
        int t = s - l;                       // timestep for this layer at this step
        if (t < 0 || t >= S_LEN) continue;   // uniform per CTA

        unsigned long long acc[4][2];
        #pragma unroll
        for (int ri = 0; ri < 4; ri++) {
            acc[ri][0] = pack2(bias[0], bias[1]);
            acc[ri][1] = pack2(bias[2], bias[3]);
        }

        // feed-forward input: x_t for layer 0, else previous layer's output (prev parity)
        const float* A0 = (l == 0) ? (x + (size_t)t * BATCH * HID)
                                   : &g_hbuf[(s + 1) & 1][l - 1][0][0];
        // recurrent input: h_0 at t==0, else own output from previous step (prev parity)
        const float* A1 = (t == 0) ? (h0 + (size_t)l * BATCH * HID)
                                   : &g_hbuf[(s + 1) & 1][l][0][0];

        gemm_acc(A0, Wl_ih, n0, tid, ty, tx, acc, At, Wt);
        gemm_acc(A1, Wl_hh, n0, tid, ty, tx, acc, At, Wt);

        float* hb = &g_hbuf[s & 1][l][0][0];
        #pragma unroll
        for (int ri = 0; ri < 4; ri++) {
            float2 v0 = unpack2(acc[ri][0]);
            float2 v1 = unpack2(acc[ri][1]);
            float4 h;
            h.x = tanhf(v0.x); h.y = tanhf(v0.y);
            h.z = tanhf(v1.x); h.w = tanhf(v1.y);
            int row = ty + 64 * ri;
            size_t off = (size_t)row * HID + n0 + tx * 4;
            *(float4*)(hb + off) = h;
            if (l == NLAYER - 1)             // y output
                *(float4*)(out + (size_t)t * BATCH * HID + off) = h;
            if (t == S_LEN - 1)              // final hidden state h_N
                *(float4*)(out + Y_ELEMS + (size_t)l * BATCH * HID + off) = h;
        }
    }
}

extern "C" void kernel_launch(void* const* d_in, const int* in_sizes, int n_in,
                              void* d_out, int out_size) {
    const float* x   = (const float*)d_in[0];
    const float* h0  = (const float*)d_in[1];
    const float* Wih = (const float*)d_in[2];
    const float* Whh = (const float*)d_in[3];
    const float* bih = (const float*)d_in[4];
    const float* bhh = (const float*)d_in[5];
    rnn_persistent<<<NCTA, NTHREADS>>>(x, h0, Wih, Whh, bih, bhh, (float*)d_out);
}

// round 5
// speedup vs baseline: 1.0038x; 1.0038x over previous
#include <cuda_runtime.h>

// MinimalRNN: 3-layer tanh RNN, S=256, B=256, H=1024.
// Persistent cooperative kernel, skewed layer pipeline (layer l computes
// timestep t = s - l at global step s), one grid barrier per global step.
// fp32 compute via packed fma.rn.f32x2 (2 MACs / instruction).

#define S_LEN   256
#define BATCH   256
#define HID     1024
#define NLAYER  3
#define NT      16                 // output columns per CTA
#define TPL     (HID / NT)         // 64 tiles per layer
#define NCTA    (NLAYER * TPL)     // 192
#define NTHREADS 256
#define KC      32                 // K-chunk staged in SMEM
#define ASTR    (KC + 4)           // 36 floats: A-tile row stride (pad)
#define WSTR    (NT + 4)           // 20 floats: W-tile row stride (pad)

#define Y_ELEMS ((size_t)S_LEN * BATCH * HID)

// Double-buffered hidden state: parity = global step s & 1.
__device__ __align__(16) float g_hbuf[2][NLAYER][BATCH][HID];
__device__ unsigned g_count = 0;
__device__ unsigned g_gen   = 0;

__device__ __forceinline__ unsigned ld_acq(const unsigned* p) {
    unsigned v;
    asm volatile("ld.acquire.gpu.global.u32 %0, [%1];" : "=r"(v) : "l"(p) : "memory");
    return v;
}

__device__ __forceinline__ void grid_barrier() {
    __syncthreads();
    if (threadIdx.x == 0) {
        __threadfence();
        unsigned gen = ld_acq(&g_gen);     // read BEFORE arriving
        __threadfence();
        unsigned ticket = atomicAdd(&g_count, 1u);
        if (ticket == NCTA - 1) {
            atomicExch(&g_count, 0u);      // reset before release
            __threadfence();
            atomicAdd(&g_gen, 1u);
        } else {
            while (ld_acq(&g_gen) == gen) { __nanosleep(64); }
        }
        __threadfence();
    }
    __syncthreads();
}

// ---- packed f32x2 helpers ----
__device__ __forceinline__ void ffma2(unsigned long long& d,
                                      unsigned long long a,
                                      unsigned long long b) {
    asm volatile("fma.rn.f32x2 %0, %1, %2, %0;" : "+l"(d) : "l"(a), "l"(b));
}
__device__ __forceinline__ unsigned long long splat2(float v) {
    unsigned long long r;
    asm("mov.b64 %0, {%1, %1};" : "=l"(r) : "f"(v));
    return r;
}
__device__ __forceinline__ unsigned long long pack2(float a, float b) {
    unsigned long long r;
    asm("mov.b64 %0, {%1, %2};" : "=l"(r) : "f"(a), "f"(b));
    return r;
}
__device__ __forceinline__ float2 unpack2(unsigned long long v) {
    float2 f;
    asm("mov.b64 {%0, %1}, %2;" : "=f"(f.x), "=f"(f.y) : "l"(v));
    return f;
}

// Accumulate acc[4 rows][2 col-pairs] += A[256 x 1024] * W[n0..n0+15][1024]^T
// A rows r = ty + 64*ri, cols c = n0 + tx*4 + {0..3}.
__device__ __forceinline__ void gemm_acc(
    const float* __restrict__ A,   // [BATCH][HID] activations (L1-bypassed reads)
    const float* __restrict__ W,   // [HID][HID] weight matrix (row-major, row = out col)
    int n0, int tid, int ty, int tx,
    unsigned long long acc[4][2],
    float At[BATCH][ASTR], float Wt[KC][WSTR])
{
    const int arow = tid >> 3;     // 0..31
    const int aq   = tid & 7;      // 0..7 : float4 index within KC
    const int wc   = tid & 15;     // weight col within tile
    const int wq   = tid >> 4;     // 0..7 when tid < 128

    for (int kc = 0; kc < HID; kc += KC) {
        // stage A chunk [256 x KC]: 8 lanes cover one row's 128B -> coalesced
        #pragma unroll
        for (int it = 0; it < 8; it++) {
            int row = arow + 32 * it;
            float4 v = __ldcg((const float4*)(A + (size_t)row * HID + kc + aq * 4));
            *(float4*)&At[row][aq * 4] = v;
        }
        // stage W chunk transposed: Wt[kk][c] = W[n0+c][kc+kk]
        if (tid < 128) {
            float4 wv = __ldg((const float4*)(W + (size_t)(n0 + wc) * HID + kc + wq * 4));
            Wt[wq * 4 + 0][wc] = wv.x;
            Wt[wq * 4 + 1][wc] = wv.y;
            Wt[wq * 4 + 2][wc] = wv.z;
            Wt[wq * 4 + 3][wc] = wv.w;
        }
        __syncthreads();

        #pragma unroll
        for (int k4 = 0; k4 < KC; k4 += 4) {
            ulonglong2 wp[4];                     // wp[j] = W cols (c0,c1),(c2,c3) at k4+j
            #pragma unroll
            for (int j = 0; j < 4; j++)
                wp[j] = *(const ulonglong2*)&Wt[k4 + j][tx * 4];
            float4 av[4];                         // av[ri] = A[row_ri][k4..k4+3]
            #pragma unroll
            for (int ri = 0; ri < 4; ri++)
                av[ri] = *(const float4*)&At[ty + 64 * ri][k4];
            #pragma unroll
            for (int j = 0; j < 4; j++) {
                #pragma unroll
                for (int ri = 0; ri < 4; ri++) {
                    float a = ((const float*)&av[ri])[j];
                    unsigned long long as = splat2(a);
                    ffma2(acc[ri][0], as, wp[j].x);
                    ffma2(acc[ri][1], as, wp[j].y);
                }
            }
        }
        __syncthreads();
    }
}

extern "C" __global__ void __launch_bounds__(NTHREADS, 2)
rnn_persistent(const float* __restrict__ x,   // [S][B][H]
               const float* __restrict__ h0,  // [L][B][H]
               const float* __restrict__ Wih, // [L][H][H]
               const float* __restrict__ Whh, // [L][H][H]
               const float* __restrict__ bih, // [L][H]
               const float* __restrict__ bhh, // [L][H]
               float* __restrict__ out)       // [S*B*H + L*B*H]
{
    __shared__ float At[BATCH][ASTR];
    __shared__ float Wt[KC][WSTR];

    const int tid = threadIdx.x;
    const int ty  = tid >> 2;      // 0..63 : batch-row group
    const int tx  = tid & 3;       // 0..3  : col group (4 cols each)
    const int l   = blockIdx.x / TPL;
    const int n0  = (blockIdx.x % TPL) * NT;

    const float* Wl_ih = Wih + (size_t)l * HID * HID;
    const float* Wl_hh = Whh + (size_t)l * HID * HID;

    float bias[4];
    #pragma unroll
    for (int j = 0; j < 4; j++) {
        int c = n0 + tx * 4 + j;
        bias[j] = __ldg(&bih[l * HID + c]) + __ldg(&bhh[l * HID + c]);
    }

    for (int s = 0; s < S_LEN + NLAYER - 1; s++) {
        if (s > 0) grid_barrier();
        int t = s - l;                       // timestep for this layer at this step
        if (t < 0 || t >= S_LEN) continue;   // uniform per CTA

        unsigned long long acc[4][2];
        #pragma unroll
        for (int ri = 0; ri < 4; ri++) {
            acc[ri][0] = pack2(bias[0], bias[1]);
            acc[ri][1] = pack2(bias[2], bias[3]);
        }

        // feed-forward input: x_t for layer 0, else previous layer's output (prev parity)
        const float* A0 = (l == 0) ? (x + (size_t)t * BATCH * HID)
                                   : &g_hbuf[(s + 1) & 1][l - 1][0][0];
        // recurrent input: h_0 at t==0, else own output from previous step (prev parity)
        const float* A1 = (t == 0) ? (h0 + (size_t)l * BATCH * HID)
                                   : &g_hbuf[(s + 1) & 1][l][0][0];

        gemm_acc(A0, Wl_ih, n0, tid, ty, tx, acc, At, Wt);
        gemm_acc(A1, Wl_hh, n0, tid, ty, tx, acc, At, Wt);

        float* hb = &g_hbuf[s & 1][l][0][0];
        #pragma unroll
        for (int ri = 0; ri < 4; ri++) {
            float2 v0 = unpack2(acc[ri][0]);
            float2 v1 = unpack2(acc[ri][1]);
            float4 h;
            h.x = tanhf(v0.x); h.y = tanhf(v0.y);
            h.z = tanhf(v1.x); h.w = tanhf(v1.y);
            int row = ty + 64 * ri;
            size_t off = (size_t)row * HID + n0 + tx * 4;
            *(float4*)(hb + off) = h;
            if (l == NLAYER - 1)             // y output
                *(float4*)(out + (size_t)t * BATCH * HID + off) = h;
            if (t == S_LEN - 1)              // final hidden state h_N
                *(float4*)(out + Y_ELEMS + (size_t)l * BATCH * HID + off) = h;
        }
    }
}

extern "C" void kernel_launch(void* const* d_in, const int* in_sizes, int n_in,
                              void* d_out, int out_size) {
    const float* x   = (const float*)d_in[0];
    const float* h0  = (const float*)d_in[1];
    const float* Wih = (const float*)d_in[2];
    const float* Whh = (const float*)d_in[3];
    const float* bih = (const float*)d_in[4];
    const float* bhh = (const float*)d_in[5];
    rnn_persistent<<<NCTA, NTHREADS>>>(x, h0, Wih, Whh, bih, bhh, (float*)d_out);
}

// round 7
// speedup vs baseline: 1.3708x; 1.3656x over previous
#include <cuda_runtime.h>
#include <cuda_bf16.h>
#include <cstdint>
#include <cstddef>

// MinimalRNN 3-layer tanh RNN, S=256, B=256, H=1024.
// Persistent kernel, skewed layer pipeline (layer l computes t = s - l).
// Arch-specific pass (sm_103a): tcgen05 bf16 3-pass (hi/lo split) GEMM.
// Base pass (sm_103): SIMT fp32x2 fallback, same launch shape.

#if defined(__CUDA_ARCH_FEAT_SM103_ALL) || defined(__CUDA_ARCH_FEAT_SM100_ALL) || \
    defined(__CUDA_ARCH_FEAT_SM101_ALL) || defined(__CUDA_ARCH_SPECIFIC__)
#define TC_OK 1
#endif
#if !defined(__CUDA_ARCH__) || defined(TC_OK)
#define COMPILE_TC 1          // host pass + arch-specific device pass
#endif

#define S_LEN   256
#define BATCH   256
#define HID     1024
#define NLAYER  3
#define NT      64
#define TPL     (HID / NT)          // 16
#define NCTA    (NLAYER * TPL)      // 48
#define NTHREADS 256
#define KC      64                  // k elems per chunk (128B bf16 rows)
#define NCHUNK  32                  // 2 GEMMs x 16 chunks
#define BH      ((size_t)BATCH * HID)
#define Y_ELEMS ((size_t)S_LEN * BATCH * HID)

// stage buffer layout (bytes within one buffer; all 1024-aligned)
#define OFF_AHI 0                   // A hi: 256 rows x 128B
#define OFF_ALO 32768               // A lo
#define OFF_WHI 65536               // W hi: 64 rows x 128B
#define OFF_WLO 73728
#define BUFSZ   81920
#define SMEM_DYN (2 * BUFSZ + 1024)

// idesc kind::f16: dtype=F32(1<<4) atype=BF16(1<<7) btype=BF16(1<<10)
// N/8=8 (<<17), M/16=8 (<<24)
#define IDESC 0x08100490u

// ---------------- global scratch ----------------
__device__ __align__(16) __nv_bfloat16 g_w_hi[2u * NLAYER * HID * HID];
__device__ __align__(16) __nv_bfloat16 g_w_lo[2u * NLAYER * HID * HID];
__device__ __align__(16) __nv_bfloat16 g_h_hi[2][NLAYER][BATCH][HID];
__device__ __align__(16) __nv_bfloat16 g_h_lo[2][NLAYER][BATCH][HID];
__device__ __align__(16) float         g_hf[2][NLAYER][BATCH][HID];  // fallback
__device__ unsigned g_count = 0;
__device__ unsigned g_gen   = 0;

// ---------------- generic helpers ----------------
__device__ __forceinline__ uint32_t smem_u32(const void* p) {
    uint32_t a;
    asm("{ .reg .u64 t; cvta.to.shared.u64 t, %1; cvt.u32.u64 %0, t; }"
        : "=r"(a) : "l"(p));
    return a;
}
__device__ __forceinline__ uint32_t swz(uint32_t off) {   // SW128
    return off ^ ((off >> 3) & 0x70);
}
__device__ __forceinline__ void sts128(uint32_t addr, uint4 v) {
    asm volatile("st.shared.v4.b32 [%0], {%1,%2,%3,%4};"
                 :: "r"(addr), "r"(v.x), "r"(v.y), "r"(v.z), "r"(v.w) : "memory");
}
__device__ __forceinline__ uint64_t mkdesc(uint32_t addr) { // SW128, LBO=1, SBO=64
    return ((uint64_t)2 << 61) | ((uint64_t)1 << 46) | ((uint64_t)64 << 32)
         | ((uint64_t)1 << 16) | ((addr >> 4) & 0x3FFF);
}
__device__ __forceinline__ uint32_t pkbf(__nv_bfloat16 a, __nv_bfloat16 b) {
    __nv_bfloat162 t = __halves2bfloat162(a, b);
    return *reinterpret_cast<uint32_t*>(&t);
}
__device__ __forceinline__ void split2(float x, float y, uint32_t& h, uint32_t& l) {
    __nv_bfloat16 hx = __float2bfloat16(x), hy = __float2bfloat16(y);
    __nv_bfloat16 lx = __float2bfloat16(x - __bfloat162float(hx));
    __nv_bfloat16 ly = __float2bfloat16(y - __bfloat162float(hy));
    h = pkbf(hx, hy); l = pkbf(lx, ly);
}

// ---------------- grid barrier (both paths) ----------------
__device__ __forceinline__ unsigned ld_acq(const unsigned* p) {
    unsigned v;
    asm volatile("ld.acquire.gpu.global.u32 %0, [%1];" : "=r"(v) : "l"(p) : "memory");
    return v;
}
__device__ __forceinline__ void grid_barrier() {
    __syncthreads();
    if (threadIdx.x == 0) {
        __threadfence();
        unsigned gen = ld_acq(&g_gen);
        __threadfence();
        unsigned ticket = atomicAdd(&g_count, 1u);
        if (ticket == NCTA - 1) {
            atomicExch(&g_count, 0u);
            __threadfence();
            atomicAdd(&g_gen, 1u);
        } else {
            while (ld_acq(&g_gen) == gen) { __nanosleep(64); }
        }
        __threadfence();
    }
    __syncthreads();
}

// ---------------- packed f32x2 (fallback path) ----------------
__device__ __forceinline__ void ffma2(unsigned long long& d,
                                      unsigned long long a, unsigned long long b) {
    asm volatile("fma.rn.f32x2 %0, %1, %2, %0;" : "+l"(d) : "l"(a), "l"(b));
}
__device__ __forceinline__ unsigned long long splat2(float v) {
    unsigned long long r;
    asm("mov.b64 %0, {%1, %1};" : "=l"(r) : "f"(v));
    return r;
}
__device__ __forceinline__ unsigned long long pack2(float a, float b) {
    unsigned long long r;
    asm("mov.b64 %0, {%1, %2};" : "=l"(r) : "f"(a), "f"(b));
    return r;
}
__device__ __forceinline__ float2 unpack2(unsigned long long v) {
    float2 f;
    asm("mov.b64 {%0, %1}, %2;" : "=f"(f.x), "=f"(f.y) : "l"(v));
    return f;
}

#define FB_KC   32
#define FB_ASTR 36
#define FB_WSTR 20
__device__ __forceinline__ void simt_gemm(
    const float* __restrict__ A, const float* __restrict__ W,
    int n0, int tid, int ty, int tx,
    unsigned long long acc[4][2],
    float (*At)[FB_ASTR], float (*Wt)[FB_WSTR])
{
    const int arow = tid >> 3, aq = tid & 7;
    const int wc = tid & 15, wq = tid >> 4;
    for (int kc = 0; kc < HID; kc += FB_KC) {
        #pragma unroll
        for (int it = 0; it < 8; it++) {
            int row = arow + 32 * it;
            float4 v = __ldcg((const float4*)(A + (size_t)row * HID + kc + aq * 4));
            *(float4*)&At[row][aq * 4] = v;
        }
        if (tid < 128) {
            float4 wv = __ldg((const float4*)(W + (size_t)(n0 + wc) * HID + kc + wq * 4));
            Wt[wq * 4 + 0][wc] = wv.x; Wt[wq * 4 + 1][wc] = wv.y;
            Wt[wq * 4 + 2][wc] = wv.z; Wt[wq * 4 + 3][wc] = wv.w;
        }
        __syncthreads();
        #pragma unroll
        for (int k4 = 0; k4 < FB_KC; k4 += 4) {
            ulonglong2 wp[4];
            #pragma unroll
            for (int j = 0; j < 4; j++)
                wp[j] = *(const ulonglong2*)&Wt[k4 + j][tx * 4];
            float4 av[4];
            #pragma unroll
            for (int ri = 0; ri < 4; ri++)
                av[ri] = *(const float4*)&At[ty + 64 * ri][k4];
            #pragma unroll
            for (int j = 0; j < 4; j++) {
                #pragma unroll
                for (int ri = 0; ri < 4; ri++) {
                    unsigned long long as = splat2(((const float*)&av[ri])[j]);
                    ffma2(acc[ri][0], as, wp[j].x);
                    ffma2(acc[ri][1], as, wp[j].y);
                }
            }
        }
        __syncthreads();
    }
}

// ---------------- tcgen05 wrappers (arch-specific pass only) ----------------
#if defined(COMPILE_TC)
#define MBARRIER_INIT(addr, cnt) \
    asm volatile("mbarrier.init.shared.b64 [%0], %1;" :: "r"(addr), "r"(cnt) : "memory")
#define MBAR_WAIT(addr, parity) do {                                            \
    uint32_t _done;                                                             \
    asm volatile("{\n\t.reg .pred p;\n\t"                                       \
        "mbarrier.try_wait.parity.acquire.cta.shared::cta.b64 p, [%1], %2;\n\t" \
        "selp.b32 %0, 1, 0, p;\n\t}"                                            \
        : "=r"(_done) : "r"(addr), "r"(parity) : "memory");                     \
    if (!_done) {                                                               \
        asm volatile("{\n\t.reg .pred P1;\n\t"                                  \
            "WL_%=:\n\t"                                                        \
            "mbarrier.try_wait.parity.acquire.cta.shared::cta.b64 P1, [%0], %1, 0x989680;\n\t" \
            "@P1 bra.uni WD_%=;\n\t"                                            \
            "bra.uni WL_%=;\n\t"                                                \
            "WD_%=:\n\t}" :: "r"(addr), "r"(parity) : "memory");                \
    }                                                                           \
} while (0)

__device__ __forceinline__ void tc_alloc(uint32_t dst_smem, uint32_t ncols) {
    asm volatile("tcgen05.alloc.cta_group::1.sync.aligned.shared::cta.b32 [%0], %1;"
                 :: "r"(dst_smem), "r"(ncols) : "memory");
}
__device__ __forceinline__ void tc_dealloc(uint32_t tmem, uint32_t ncols) {
    asm volatile("tcgen05.dealloc.cta_group::1.sync.aligned.b32 %0, %1;"
                 :: "r"(tmem), "r"(ncols));
}
__device__ __forceinline__ void tc_relinquish() {
    asm volatile("tcgen05.relinquish_alloc_permit.cta_group::1.sync.aligned;");
}
__device__ __forceinline__ void tc_mma_ss(uint32_t d, uint64_t ad, uint64_t bd,
                                          uint32_t idesc, uint32_t en) {
    asm volatile("{\n\t.reg .pred p;\n\tsetp.ne.u32 p, %5, 0;\n\t"
        "tcgen05.mma.cta_group::1.kind::f16 [%0], %1, %2, %3, {%4,%4,%4,%4}, p;\n\t}"
        :: "r"(d), "l"(ad), "l"(bd), "r"(idesc), "r"(0u), "r"(en) : "memory");
}
__device__ __forceinline__ void tc_commit(uint32_t mbar) {
    asm volatile("tcgen05.commit.cta_group::1.mbarrier::arrive::one.shared::cluster.b64 [%0];"
                 :: "r"(mbar) : "memory");
}
#define TC_FENCE_BEFORE() asm volatile("tcgen05.fence::before_thread_sync;" ::: "memory")
#define TC_FENCE_AFTER()  asm volatile("tcgen05.fence::after_thread_sync;"  ::: "memory")
#define TC_WAIT_LD()      asm volatile("tcgen05.wait::ld.sync.aligned;" ::: "memory")
#define FENCE_ASYNC()     asm volatile("fence.proxy.async.shared::cta;" ::: "memory")

#define LDTM_X32(r, a)                                                          \
    asm volatile("tcgen05.ld.sync.aligned.32x32b.x32.b32 "                      \
        "{%0,%1,%2,%3,%4,%5,%6,%7,%8,%9,%10,%11,%12,%13,%14,%15,"               \
        "%16,%17,%18,%19,%20,%21,%22,%23,%24,%25,%26,%27,%28,%29,%30,%31}, [%32];" \
        : "=r"((r)[0]),"=r"((r)[1]),"=r"((r)[2]),"=r"((r)[3]),                  \
          "=r"((r)[4]),"=r"((r)[5]),"=r"((r)[6]),"=r"((r)[7]),                  \
          "=r"((r)[8]),"=r"((r)[9]),"=r"((r)[10]),"=r"((r)[11]),                \
          "=r"((r)[12]),"=r"((r)[13]),"=r"((r)[14]),"=r"((r)[15]),              \
          "=r"((r)[16]),"=r"((r)[17]),"=r"((r)[18]),"=r"((r)[19]),              \
          "=r"((r)[20]),"=r"((r)[21]),"=r"((r)[22]),"=r"((r)[23]),              \
          "=r"((r)[24]),"=r"((r)[25]),"=r"((r)[26]),"=r"((r)[27]),              \
          "=r"((r)[28]),"=r"((r)[29]),"=r"((r)[30]),"=r"((r)[31])               \
        : "r"(a))
#endif // COMPILE_TC

// ---------------- weight pre-split (compiles everywhere) ----------------
extern "C" __global__ void split_weights(const float* __restrict__ Wih,
                                         const float* __restrict__ Whh) {
    size_t tot4 = (size_t)NLAYER * HID * HID / 4;
    size_t i4 = (size_t)blockIdx.x * blockDim.x + threadIdx.x;
    if (i4 >= tot4) return;
    float4 a = __ldg((const float4*)Wih + i4);
    float4 b = __ldg((const float4*)Whh + i4);
    uint2 h, l;
    split2(a.x, a.y, h.x, l.x); split2(a.z, a.w, h.y, l.y);
    ((uint2*)g_w_hi)[i4] = h;  ((uint2*)g_w_lo)[i4] = l;
    split2(b.x, b.y, h.x, l.x); split2(b.z, b.w, h.y, l.y);
    ((uint2*)g_w_hi)[tot4 + i4] = h;  ((uint2*)g_w_lo)[tot4 + i4] = l;
}

// ---------------- persistent RNN kernel ----------------
extern "C" __global__ void __launch_bounds__(NTHREADS, 1)
rnn_tc(const float* __restrict__ x,    // [S][B][H]
       const float* __restrict__ h0,   // [L][B][H]
       const float* __restrict__ Wih,  // [L][H][H] (fallback path only)
       const float* __restrict__ Whh,  // [L][H][H] (fallback path only)
       const float* __restrict__ bih,  // [L][H]
       const float* __restrict__ bhh,  // [L][H]
       float* __restrict__ out)        // y [S*B*H] ++ h_N [L*B*H]
{
#if defined(COMPILE_TC)
    // ================= tcgen05 bf16 3-pass path =================
    (void)Wih; (void)Whh;
    extern __shared__ __align__(1024) char dynsm[];
    __shared__ __align__(16) uint64_t mbar[2];
    __shared__ uint32_t tmem_ptr_sm;
    __shared__ float bias_sm[NT];

    const int tid  = threadIdx.x;
    const int wid  = tid >> 5;
    const int lane = tid & 31;
    const int l    = blockIdx.x / TPL;
    const int n0   = (blockIdx.x % TPL) * NT;

    uint32_t smbase = smem_u32(dynsm);
    smbase = (smbase + 1023u) & ~1023u;
    const uint32_t mbar_a[2] = { smem_u32(&mbar[0]), smem_u32(&mbar[1]) };

    if (wid == 0) tc_alloc(smem_u32(&tmem_ptr_sm), 128);
    if (tid == 0) { MBARRIER_INIT(mbar_a[0], 1); MBARRIER_INIT(mbar_a[1], 1); }
    if (tid < NT)
        bias_sm[tid] = __ldg(&bih[l * HID + n0 + tid]) + __ldg(&bhh[l * HID + n0 + tid]);
    __syncthreads();
    const uint32_t tmem = tmem_ptr_sm;
    if (wid == 0) tc_relinquish();

    unsigned u0 = 0, u1 = 0;

    for (int s = 0; s < S_LEN + NLAYER - 1; s++) {
        if (s > 0) grid_barrier();
        const int t = s - l;
        if (t < 0 || t >= S_LEN) continue;
        const int pp = (s + 1) & 1;

        const float*         a0f = (l == 0) ? (x + (size_t)t * BH) : nullptr;
        const __nv_bfloat16* a0h = &g_h_hi[pp][(l == 0) ? 0 : (l - 1)][0][0];
        const __nv_bfloat16* a0l = &g_h_lo[pp][(l == 0) ? 0 : (l - 1)][0][0];
        const float*         a1f = (t == 0) ? (h0 + (size_t)l * BH) : nullptr;
        const __nv_bfloat16* a1h = &g_h_hi[pp][l][0][0];
        const __nv_bfloat16* a1l = &g_h_lo[pp][l][0][0];

        for (int ch = 0; ch < NCHUNK; ch++) {
            const int b    = ch & 1;
            const uint32_t bb = smbase + (uint32_t)b * BUFSZ;
            const int g    = ch >> 4;            // 0: ih, 1: hh
            const int k0   = (ch & 15) * KC;

            if (ch >= 2) {
                if (b == 0) { MBAR_WAIT(mbar_a[0], u0 & 1); u0++; }
                else        { MBAR_WAIT(mbar_a[1], u1 & 1); u1++; }
            }

            // ---- stage A [256 x 64] hi+lo (row = tid) ----
            {
                const int row = tid;
                const uint32_t rb = (uint32_t)row * 128u;
                const float* af = g ? a1f : a0f;
                if (af) {
                    const float4* src = (const float4*)(af + (size_t)row * HID + k0);
                    #pragma unroll
                    for (int q = 0; q < 8; q++) {
                        float4 p0 = __ldg(src + 2 * q);
                        float4 p1 = __ldg(src + 2 * q + 1);
                        uint4 hv, lv;
                        split2(p0.x, p0.y, hv.x, lv.x);
                        split2(p0.z, p0.w, hv.y, lv.y);
                        split2(p1.x, p1.y, hv.z, lv.z);
                        split2(p1.z, p1.w, hv.w, lv.w);
                        uint32_t so = swz(rb + q * 16u);
                        sts128(bb + OFF_AHI + so, hv);
                        sts128(bb + OFF_ALO + so, lv);
                    }
                } else {
                    const uint4* sh = (const uint4*)((g ? a1h : a0h) + (size_t)row * HID + k0);
                    const uint4* sl = (const uint4*)((g ? a1l : a0l) + (size_t)row * HID + k0);
                    #pragma unroll
                    for (int q = 0; q < 8; q++) {
                        uint32_t so = swz(rb + q * 16u);
                        sts128(bb + OFF_AHI + so, __ldcg(sh + q));
                        sts128(bb + OFF_ALO + so, __ldcg(sl + q));
                    }
                }
            }
            // ---- stage W [64 x 64] hi+lo ----
            {
                const int row = tid >> 2, qq = tid & 3;
                const size_t wbase = (((size_t)g * NLAYER + l) * HID + (n0 + row)) * HID + k0;
                const uint4* wh = (const uint4*)(g_w_hi + wbase);
                const uint4* wl = (const uint4*)(g_w_lo + wbase);
                #pragma unroll
                for (int e = 0; e < 2; e++) {
                    int q = qq * 2 + e;
                    uint32_t so = swz((uint32_t)row * 128u + q * 16u);
                    sts128(bb + OFF_WHI + so, __ldg(wh + q));
                    sts128(bb + OFF_WLO + so, __ldg(wl + q));
                }
            }
            FENCE_ASYNC();
            __syncthreads();

            // ---- MMA: 2 M-halves x 3 passes x 4 k-steps ----
            if (wid == 0) {
                TC_FENCE_AFTER();
                if (lane == 0) {
                    #pragma unroll
                    for (int mh = 0; mh < 2; mh++) {
                        #pragma unroll
                        for (int ps = 0; ps < 3; ps++) {
                            uint32_t ao = (ps == 2 ? OFF_ALO : OFF_AHI) + mh * 16384u;
                            uint32_t wo = (ps == 1 ? OFF_WLO : OFF_WHI);
                            uint64_t ad = mkdesc(bb + ao);
                            uint64_t bd = mkdesc(bb + wo);
                            #pragma unroll
                            for (int ks = 0; ks < 4; ks++) {
                                uint32_t en = !(ch == 0 && ps == 0 && ks == 0);
                                tc_mma_ss(tmem + mh * 64, ad + ks * 2, bd + ks * 2,
                                          IDESC, en);
                            }
                        }
                    }
                    tc_commit(mbar_a[b]);
                }
            }
        }

        MBAR_WAIT(mbar_a[0], u0 & 1); u0++;
        MBAR_WAIT(mbar_a[1], u1 & 1); u1++;
        TC_FENCE_AFTER();

        // ---- epilogue: LDTM -> +bias -> tanh -> split/store ----
        {
            const int mh   = wid >> 2;
            const int row  = mh * 128 + (wid & 3) * 32 + lane;
            uint32_t r[64];
            LDTM_X32(r, tmem + mh * 64);
            LDTM_X32(r + 32, tmem + mh * 64 + 32);
            TC_WAIT_LD();

            float hv[64];
            #pragma unroll
            for (int c = 0; c < 64; c++)
                hv[c] = tanhf(__uint_as_float(r[c]) + bias_sm[c]);

            const int wp = s & 1;
            uint32_t hip[32], lop[32];
            #pragma unroll
            for (int c = 0; c < 64; c += 2)
                split2(hv[c], hv[c + 1], hip[c >> 1], lop[c >> 1]);
            uint4* dh = (uint4*)&g_h_hi[wp][l][row][n0];
            uint4* dl = (uint4*)&g_h_lo[wp][l][row][n0];
            #pragma unroll
            for (int q = 0; q < 8; q++) {
                dh[q] = make_uint4(hip[4*q], hip[4*q+1], hip[4*q+2], hip[4*q+3]);
                dl[q] = make_uint4(lop[4*q], lop[4*q+1], lop[4*q+2], lop[4*q+3]);
            }
            if (l == NLAYER - 1) {
                float4* yb = (float4*)(out + (size_t)t * BH + (size_t)row * HID + n0);
                #pragma unroll
                for (int q = 0; q < 16; q++)
                    yb[q] = make_float4(hv[4*q], hv[4*q+1], hv[4*q+2], hv[4*q+3]);
            }
            if (t == S_LEN - 1) {
                float4* hb = (float4*)(out + Y_ELEMS + (size_t)l * BH + (size_t)row * HID + n0);
                #pragma unroll
                for (int q = 0; q < 16; q++)
                    hb[q] = make_float4(hv[4*q], hv[4*q+1], hv[4*q+2], hv[4*q+3]);
            }
            TC_FENCE_BEFORE();
        }
    }

    __syncthreads();
    if (wid == 0) tc_dealloc(tmem, 128);

#else
    // ================= SIMT fp32x2 fallback (base sm_103 pass) =================
    extern __shared__ __align__(16) char dynsm[];
    float (*At)[FB_ASTR] = (float(*)[FB_ASTR])dynsm;
    float (*Wt)[FB_WSTR] = (float(*)[FB_WSTR])(dynsm + sizeof(float) * BATCH * FB_ASTR);

    const int tid = threadIdx.x;
    const int ty  = tid >> 2;
    const int tx  = tid & 3;
    const int l   = blockIdx.x / TPL;
    const int nb  = (blockIdx.x % TPL) * NT;

    const float* Wl_ih = Wih + (size_t)l * HID * HID;
    const float* Wl_hh = Whh + (size_t)l * HID * HID;

    for (int s = 0; s < S_LEN + NLAYER - 1; s++) {
        if (s > 0) grid_barrier();
        int t = s - l;
        if (t < 0 || t >= S_LEN) continue;

        const float* A0 = (l == 0) ? (x + (size_t)t * BH) : &g_hf[(s + 1) & 1][l - 1][0][0];
        const float* A1 = (t == 0) ? (h0 + (size_t)l * BH) : &g_hf[(s + 1) & 1][l][0][0];

        for (int st = 0; st < NT / 16; st++) {
            const int n0 = nb + st * 16;
            float bias[4];
            #pragma unroll
            for (int j = 0; j < 4; j++) {
                int c = n0 + tx * 4 + j;
                bias[j] = __ldg(&bih[l * HID + c]) + __ldg(&bhh[l * HID + c]);
            }
            unsigned long long acc[4][2];
            #pragma unroll
            for (int ri = 0; ri < 4; ri++) {
                acc[ri][0] = pack2(bias[0], bias[1]);
                acc[ri][1] = pack2(bias[2], bias[3]);
            }
            simt_gemm(A0, Wl_ih, n0, tid, ty, tx, acc, At, Wt);
            simt_gemm(A1, Wl_hh, n0, tid, ty, tx, acc, At, Wt);

            float* hb = &g_hf[s & 1][l][0][0];
            #pragma unroll
            for (int ri = 0; ri < 4; ri++) {
                float2 v0 = unpack2(acc[ri][0]);
                float2 v1 = unpack2(acc[ri][1]);
                float4 h;
                h.x = tanhf(v0.x); h.y = tanhf(v0.y);
                h.z = tanhf(v1.x); h.w = tanhf(v1.y);
                int row = ty + 64 * ri;
                size_t off = (size_t)row * HID + n0 + tx * 4;
                *(float4*)(hb + off) = h;
                if (l == NLAYER - 1)
                    *(float4*)(out + (size_t)t * BH + off) = h;
                if (t == S_LEN - 1)
                    *(float4*)(out + Y_ELEMS + (size_t)l * BH + off) = h;
            }
        }
    }
#endif
}

extern "C" void kernel_launch(void* const* d_in, const int* in_sizes, int n_in,
                              void* d_out, int out_size) {
    const float* x   = (const float*)d_in[0];
    const float* h0  = (const float*)d_in[1];
    const float* Wih = (const float*)d_in[2];
    const float* Whh = (const float*)d_in[3];
    const float* bih = (const float*)d_in[4];
    const float* bhh = (const float*)d_in[5];

    cudaFuncSetAttribute(rnn_tc, cudaFuncAttributeMaxDynamicSharedMemorySize, SMEM_DYN);

    size_t tot4 = (size_t)NLAYER * HID * HID / 4;
    split_weights<<<(unsigned)((tot4 + 255) / 256), 256>>>(Wih, Whh);
    rnn_tc<<<NCTA, NTHREADS, SMEM_DYN>>>(x, h0, Wih, Whh, bih, bhh, (float*)d_out);
}

// round 9
// speedup vs baseline: 1.6269x; 1.1868x over previous
#include <cuda_runtime.h>
#include <cuda_bf16.h>
#include <cstdint>
#include <cstddef>

// MinimalRNN 3-layer tanh RNN, S=256, B=256, H=1024.
// Persistent kernel, skewed layer pipeline (layer l computes t = s - l).
// sm_103a pass: tcgen05 bf16 3-pass (hi/lo split), TS mode (A in TMEM via
// STTM; W in SMEM). Base sm_103 pass: SIMT fp32x2 fallback.
// R9: reinstate fence.proxy.async (STS W -> MMA) and tcgen05.fence pair
// (STTM A -> MMA) that R8 dropped — the R8 1.1e-3 error was a visibility race.

#if defined(__CUDA_ARCH_FEAT_SM103_ALL) || defined(__CUDA_ARCH_FEAT_SM100_ALL) || \
    defined(__CUDA_ARCH_FEAT_SM101_ALL) || defined(__CUDA_ARCH_SPECIFIC__)
#define TC_OK 1
#endif
#if !defined(__CUDA_ARCH__) || defined(TC_OK)
#define COMPILE_TC 1          // host pass + arch-specific device pass
#endif

#define S_LEN   256
#define BATCH   256
#define HID     1024
#define NLAYER  3
#define NT      64
#define TPL     (HID / NT)          // 16
#define NCTA    (NLAYER * TPL)      // 48
#define NTHREADS 256
#define KC      64                  // k elems per chunk
#define NCHUNK  32                  // 2 GEMMs x 16 chunks
#define BH      ((size_t)BATCH * HID)
#define Y_ELEMS ((size_t)S_LEN * BATCH * HID)

// W stage buffers in SMEM: per buffer hi 8KB + lo 8KB
#define WBUFSZ  16384
#define OFF_WLO 8192
#define SMEM_DYN (2 * WBUFSZ + 1024)

// TMEM columns: D at 0 (128 cols), A buffers at 128 (2 x 128 cols)
#define TM_D    0
#define TM_A    128

// idesc kind::f16: dtype=F32(1<<4) atype=BF16(1<<7) btype=BF16(1<<10)
// N/8=8 (<<17), M/16=8 (<<24)
#define IDESC 0x08100490u

// ---------------- global scratch ----------------
__device__ __align__(16) __nv_bfloat16 g_w_hi[2u * NLAYER * HID * HID];
__device__ __align__(16) __nv_bfloat16 g_w_lo[2u * NLAYER * HID * HID];
__device__ __align__(16) __nv_bfloat16 g_x_hi[(size_t)S_LEN * BATCH * HID];
__device__ __align__(16) __nv_bfloat16 g_x_lo[(size_t)S_LEN * BATCH * HID];
__device__ __align__(16) __nv_bfloat16 g_h_hi[2][NLAYER][BATCH][HID];
__device__ __align__(16) __nv_bfloat16 g_h_lo[2][NLAYER][BATCH][HID];
__device__ __align__(16) float         g_hf[2][NLAYER][BATCH][HID];  // fallback
__device__ unsigned g_count = 0;
__device__ unsigned g_gen   = 0;

// ---------------- generic helpers ----------------
__device__ __forceinline__ uint32_t smem_u32(const void* p) {
    uint32_t a;
    asm("{ .reg .u64 t; cvta.to.shared.u64 t, %1; cvt.u32.u64 %0, t; }"
        : "=r"(a) : "l"(p));
    return a;
}
__device__ __forceinline__ uint32_t swz(uint32_t off) {   // SW128
    return off ^ ((off >> 3) & 0x70);
}
__device__ __forceinline__ void sts128(uint32_t addr, uint4 v) {
    asm volatile("st.shared.v4.b32 [%0], {%1,%2,%3,%4};"
                 :: "r"(addr), "r"(v.x), "r"(v.y), "r"(v.z), "r"(v.w) : "memory");
}
__device__ __forceinline__ uint64_t mkdesc(uint32_t addr) { // SW128, LBO=1, SBO=64
    return ((uint64_t)2 << 61) | ((uint64_t)1 << 46) | ((uint64_t)64 << 32)
         | ((uint64_t)1 << 16) | ((addr >> 4) & 0x3FFF);
}
__device__ __forceinline__ uint32_t pkbf(__nv_bfloat16 a, __nv_bfloat16 b) {
    __nv_bfloat162 t = __halves2bfloat162(a, b);
    return *reinterpret_cast<uint32_t*>(&t);
}
__device__ __forceinline__ void split2(float x, float y, uint32_t& h, uint32_t& l) {
    __nv_bfloat16 hx = __float2bfloat16(x), hy = __float2bfloat16(y);
    __nv_bfloat16 lx = __float2bfloat16(x - __bfloat162float(hx));
    __nv_bfloat16 ly = __float2bfloat16(y - __bfloat162float(hy));
    h = pkbf(hx, hy); l = pkbf(lx, ly);
}

// ---------------- grid barrier ----------------
__device__ __forceinline__ unsigned ld_acq(const unsigned* p) {
    unsigned v;
    asm volatile("ld.acquire.gpu.global.u32 %0, [%1];" : "=r"(v) : "l"(p) : "memory");
    return v;
}
__device__ __forceinline__ void grid_barrier() {
    __syncthreads();
    if (threadIdx.x == 0) {
        __threadfence();
        unsigned gen = ld_acq(&g_gen);
        __threadfence();
        unsigned ticket = atomicAdd(&g_count, 1u);
        if (ticket == NCTA - 1) {
            atomicExch(&g_count, 0u);
            __threadfence();
            atomicAdd(&g_gen, 1u);
        } else {
            while (ld_acq(&g_gen) == gen) { __nanosleep(64); }
        }
        __threadfence();
    }
    __syncthreads();
}

// ---------------- packed f32x2 (fallback path) ----------------
__device__ __forceinline__ void ffma2(unsigned long long& d,
                                      unsigned long long a, unsigned long long b) {
    asm volatile("fma.rn.f32x2 %0, %1, %2, %0;" : "+l"(d) : "l"(a), "l"(b));
}
__device__ __forceinline__ unsigned long long splat2(float v) {
    unsigned long long r;
    asm("mov.b64 %0, {%1, %1};" : "=l"(r) : "f"(v));
    return r;
}
__device__ __forceinline__ unsigned long long pack2(float a, float b) {
    unsigned long long r;
    asm("mov.b64 %0, {%1, %2};" : "=l"(r) : "f"(a), "f"(b));
    return r;
}
__device__ __forceinline__ float2 unpack2(unsigned long long v) {
    float2 f;
    asm("mov.b64 {%0, %1}, %2;" : "=f"(f.x), "=f"(f.y) : "l"(v));
    return f;
}

#define FB_KC   32
#define FB_ASTR 36
#define FB_WSTR 20
__device__ __forceinline__ void simt_gemm(
    const float* __restrict__ A, const float* __restrict__ W,
    int n0, int tid, int ty, int tx,
    unsigned long long acc[4][2],
    float (*At)[FB_ASTR], float (*Wt)[FB_WSTR])
{
    const int arow = tid >> 3, aq = tid & 7;
    const int wc = tid & 15, wq = tid >> 4;
    for (int kc = 0; kc < HID; kc += FB_KC) {
        #pragma unroll
        for (int it = 0; it < 8; it++) {
            int row = arow + 32 * it;
            float4 v = __ldcg((const float4*)(A + (size_t)row * HID + kc + aq * 4));
            *(float4*)&At[row][aq * 4] = v;
        }
        if (tid < 128) {
            float4 wv = __ldg((const float4*)(W + (size_t)(n0 + wc) * HID + kc + wq * 4));
            Wt[wq * 4 + 0][wc] = wv.x; Wt[wq * 4 + 1][wc] = wv.y;
            Wt[wq * 4 + 2][wc] = wv.z; Wt[wq * 4 + 3][wc] = wv.w;
        }
        __syncthreads();
        #pragma unroll
        for (int k4 = 0; k4 < FB_KC; k4 += 4) {
            ulonglong2 wp[4];
            #pragma unroll
            for (int j = 0; j < 4; j++)
                wp[j] = *(const ulonglong2*)&Wt[k4 + j][tx * 4];
            float4 av[4];
            #pragma unroll
            for (int ri = 0; ri < 4; ri++)
                av[ri] = *(const float4*)&At[ty + 64 * ri][k4];
            #pragma unroll
            for (int j = 0; j < 4; j++) {
                #pragma unroll
                for (int ri = 0; ri < 4; ri++) {
                    unsigned long long as = splat2(((const float*)&av[ri])[j]);
                    ffma2(acc[ri][0], as, wp[j].x);
                    ffma2(acc[ri][1], as, wp[j].y);
                }
            }
        }
        __syncthreads();
    }
}

// ---------------- tcgen05 wrappers (arch-specific pass only) ----------------
#if defined(COMPILE_TC)
#define MBARRIER_INIT(addr, cnt) \
    asm volatile("mbarrier.init.shared.b64 [%0], %1;" :: "r"(addr), "r"(cnt) : "memory")
#define MBAR_WAIT(addr, parity) do {                                            \
    uint32_t _done;                                                             \
    asm volatile("{\n\t.reg .pred p;\n\t"                                       \
        "mbarrier.try_wait.parity.acquire.cta.shared::cta.b64 p, [%1], %2;\n\t" \
        "selp.b32 %0, 1, 0, p;\n\t}"                                            \
        : "=r"(_done) : "r"(addr), "r"(parity) : "memory");                     \
    if (!_done) {                                                               \
        asm volatile("{\n\t.reg .pred P1;\n\t"                                  \
            "WL_%=:\n\t"                                                        \
            "mbarrier.try_wait.parity.acquire.cta.shared::cta.b64 P1, [%0], %1, 0x989680;\n\t" \
            "@P1 bra.uni WD_%=;\n\t"                                            \
            "bra.uni WL_%=;\n\t"                                                \
            "WD_%=:\n\t}" :: "r"(addr), "r"(parity) : "memory");                \
    }                                                                           \
} while (0)

__device__ __forceinline__ void tc_alloc(uint32_t dst_smem, uint32_t ncols) {
    asm volatile("tcgen05.alloc.cta_group::1.sync.aligned.shared::cta.b32 [%0], %1;"
                 :: "r"(dst_smem), "r"(ncols) : "memory");
}
__device__ __forceinline__ void tc_dealloc(uint32_t tmem, uint32_t ncols) {
    asm volatile("tcgen05.dealloc.cta_group::1.sync.aligned.b32 %0, %1;"
                 :: "r"(tmem), "r"(ncols));
}
__device__ __forceinline__ void tc_relinquish() {
    asm volatile("tcgen05.relinquish_alloc_permit.cta_group::1.sync.aligned;");
}
// TS form: A operand in TMEM
__device__ __forceinline__ void tc_mma_ts(uint32_t d, uint32_t a, uint64_t bd,
                                          uint32_t idesc, uint32_t en) {
    asm volatile("{\n\t.reg .pred p;\n\tsetp.ne.u32 p, %5, 0;\n\t"
        "tcgen05.mma.cta_group::1.kind::f16 [%0], [%1], %2, %3, {%4,%4,%4,%4}, p;\n\t}"
        :: "r"(d), "r"(a), "l"(bd), "r"(idesc), "r"(0u), "r"(en) : "memory");
}
__device__ __forceinline__ void tc_commit(uint32_t mbar) {
    asm volatile("tcgen05.commit.cta_group::1.mbarrier::arrive::one.shared::cluster.b64 [%0];"
                 :: "r"(mbar) : "memory");
}
#define TC_FENCE_BEFORE() asm volatile("tcgen05.fence::before_thread_sync;" ::: "memory")
#define TC_FENCE_AFTER()  asm volatile("tcgen05.fence::after_thread_sync;"  ::: "memory")
#define TC_WAIT_LD()      asm volatile("tcgen05.wait::ld.sync.aligned;" ::: "memory")
#define TC_WAIT_ST()      asm volatile("tcgen05.wait::st.sync.aligned;" ::: "memory")
#define FENCE_ASYNC()     asm volatile("fence.proxy.async.shared::cta;" ::: "memory")

#define LDTM_X32(r, a)                                                          \
    asm volatile("tcgen05.ld.sync.aligned.32x32b.x32.b32 "                      \
        "{%0,%1,%2,%3,%4,%5,%6,%7,%8,%9,%10,%11,%12,%13,%14,%15,"               \
        "%16,%17,%18,%19,%20,%21,%22,%23,%24,%25,%26,%27,%28,%29,%30,%31}, [%32];" \
        : "=r"((r)[0]),"=r"((r)[1]),"=r"((r)[2]),"=r"((r)[3]),                  \
          "=r"((r)[4]),"=r"((r)[5]),"=r"((r)[6]),"=r"((r)[7]),                  \
          "=r"((r)[8]),"=r"((r)[9]),"=r"((r)[10]),"=r"((r)[11]),                \
          "=r"((r)[12]),"=r"((r)[13]),"=r"((r)[14]),"=r"((r)[15]),              \
          "=r"((r)[16]),"=r"((r)[17]),"=r"((r)[18]),"=r"((r)[19]),              \
          "=r"((r)[20]),"=r"((r)[21]),"=r"((r)[22]),"=r"((r)[23]),              \
          "=r"((r)[24]),"=r"((r)[25]),"=r"((r)[26]),"=r"((r)[27]),              \
          "=r"((r)[28]),"=r"((r)[29]),"=r"((r)[30]),"=r"((r)[31])               \
        : "r"(a))

#define STTM_X32(a, r)                                                          \
    asm volatile("tcgen05.st.sync.aligned.32x32b.x32.b32 [%0], "                \
        "{%1,%2,%3,%4,%5,%6,%7,%8,%9,%10,%11,%12,%13,%14,%15,%16,"              \
        "%17,%18,%19,%20,%21,%22,%23,%24,%25,%26,%27,%28,%29,%30,%31,%32};"     \
        :: "r"(a),                                                              \
           "r"((r)[0]),"r"((r)[1]),"r"((r)[2]),"r"((r)[3]),                     \
           "r"((r)[4]),"r"((r)[5]),"r"((r)[6]),"r"((r)[7]),                     \
           "r"((r)[8]),"r"((r)[9]),"r"((r)[10]),"r"((r)[11]),                   \
           "r"((r)[12]),"r"((r)[13]),"r"((r)[14]),"r"((r)[15]),                 \
           "r"((r)[16]),"r"((r)[17]),"r"((r)[18]),"r"((r)[19]),                 \
           "r"((r)[20]),"r"((r)[21]),"r"((r)[22]),"r"((r)[23]),                 \
           "r"((r)[24]),"r"((r)[25]),"r"((r)[26]),"r"((r)[27]),                 \
           "r"((r)[28]),"r"((r)[29]),"r"((r)[30]),"r"((r)[31])                  \
        : "memory")
#endif // COMPILE_TC

// ---------------- prelude kernels ----------------
extern "C" __global__ void split_weights(const float* __restrict__ Wih,
                                         const float* __restrict__ Whh) {
    size_t tot4 = (size_t)NLAYER * HID * HID / 4;
    size_t i4 = (size_t)blockIdx.x * blockDim.x + threadIdx.x;
    if (i4 >= tot4) return;
    float4 a = __ldg((const float4*)Wih + i4);
    float4 b = __ldg((const float4*)Whh + i4);
    uint2 h, l;
    split2(a.x, a.y, h.x, l.x); split2(a.z, a.w, h.y, l.y);
    ((uint2*)g_w_hi)[i4] = h;  ((uint2*)g_w_lo)[i4] = l;
    split2(b.x, b.y, h.x, l.x); split2(b.z, b.w, h.y, l.y);
    ((uint2*)g_w_hi)[tot4 + i4] = h;  ((uint2*)g_w_lo)[tot4 + i4] = l;
}

extern "C" __global__ void split_x(const float* __restrict__ x) {
    size_t tot4 = Y_ELEMS / 4;
    for (size_t i4 = (size_t)blockIdx.x * blockDim.x + threadIdx.x;
         i4 < tot4; i4 += (size_t)gridDim.x * blockDim.x) {
        float4 a = __ldg((const float4*)x + i4);
        uint2 h, l;
        split2(a.x, a.y, h.x, l.x); split2(a.z, a.w, h.y, l.y);
        ((uint2*)g_x_hi)[i4] = h;  ((uint2*)g_x_lo)[i4] = l;
    }
}

// seed h0 into the parity slot read at t==0 for each layer: pp = (l+1)&1
extern "C" __global__ void seed_h0(const float* __restrict__ h0) {
    size_t tot4 = (size_t)NLAYER * BH / 4;
    size_t i4 = (size_t)blockIdx.x * blockDim.x + threadIdx.x;
    if (i4 >= tot4) return;
    int l = (int)(i4 / (BH / 4));
    size_t r4 = i4 % (BH / 4);
    int pp = (l + 1) & 1;
    float4 a = __ldg((const float4*)h0 + i4);
    uint2 h, lo;
    split2(a.x, a.y, h.x, lo.x); split2(a.z, a.w, h.y, lo.y);
    ((uint2*)&g_h_hi[pp][l][0][0])[r4] = h;
    ((uint2*)&g_h_lo[pp][l][0][0])[r4] = lo;
}

// ---------------- persistent RNN kernel ----------------
extern "C" __global__ void __launch_bounds__(NTHREADS, 1)
rnn_tc(const float* __restrict__ x,    // [S][B][H]
       const float* __restrict__ h0,   // [L][B][H]
       const float* __restrict__ Wih,  // fallback path only
       const float* __restrict__ Whh,  // fallback path only
       const float* __restrict__ bih,  // [L][H]
       const float* __restrict__ bhh,  // [L][H]
       float* __restrict__ out)        // y [S*B*H] ++ h_N [L*B*H]
{
#if defined(COMPILE_TC)
    // ================= tcgen05 TS-mode 3-pass path =================
    (void)x; (void)h0; (void)Wih; (void)Whh;
    extern __shared__ __align__(1024) char dynsm[];
    __shared__ __align__(16) uint64_t mbar[2];
    __shared__ uint32_t tmem_ptr_sm;
    __shared__ float bias_sm[NT];

    const int tid  = threadIdx.x;
    const int wid  = tid >> 5;
    const int lane = tid & 31;
    const int l    = blockIdx.x / TPL;
    const int n0   = (blockIdx.x % TPL) * NT;
    const uint32_t warp_off = (uint32_t)(wid & 3) << 21;  // TMEM subpartition
    const int half = tid >> 7;                            // M-half of my A row

    uint32_t smbase = smem_u32(dynsm);
    smbase = (smbase + 1023u) & ~1023u;
    const uint32_t mbar_a[2] = { smem_u32(&mbar[0]), smem_u32(&mbar[1]) };

    if (wid == 0) tc_alloc(smem_u32(&tmem_ptr_sm), 512);
    if (tid == 0) { MBARRIER_INIT(mbar_a[0], 1); MBARRIER_INIT(mbar_a[1], 1); }
    if (tid < NT)
        bias_sm[tid] = __ldg(&bih[l * HID + n0 + tid]) + __ldg(&bhh[l * HID + n0 + tid]);
    __syncthreads();
    const uint32_t tmem = tmem_ptr_sm;
    if (wid == 0) tc_relinquish();

    unsigned u0 = 0, u1 = 0;

    for (int s = 0; s < S_LEN + NLAYER - 1; s++) {
        if (s > 0) grid_barrier();
        const int t = s - l;
        if (t < 0 || t >= S_LEN) continue;
        const int pp = (s + 1) & 1;

        // A sources (all pre-split bf16)
        const __nv_bfloat16* a0h = (l == 0) ? (g_x_hi + (size_t)t * BH)
                                            : &g_h_hi[pp][l - 1][0][0];
        const __nv_bfloat16* a0l = (l == 0) ? (g_x_lo + (size_t)t * BH)
                                            : &g_h_lo[pp][l - 1][0][0];
        const __nv_bfloat16* a1h = &g_h_hi[pp][l][0][0];
        const __nv_bfloat16* a1l = &g_h_lo[pp][l][0][0];

        for (int ch = 0; ch < NCHUNK; ch++) {
            const int b  = ch & 1;
            const int g  = ch >> 4;               // 0: ih, 1: hh
            const int k0 = (ch & 15) * KC;

            // ---- issue global loads FIRST (overlap mbar wait / prior MMA) ----
            uint32_t ah[32], al[32], wreg[16];
            {
                const size_t aoff = (size_t)tid * HID + k0;
                const uint4* sh = (const uint4*)((g ? a1h : a0h) + aoff);
                const uint4* sl = (const uint4*)((g ? a1l : a0l) + aoff);
                #pragma unroll
                for (int q = 0; q < 8; q++) {
                    uint4 v = __ldcg(sh + q);
                    ah[4*q] = v.x; ah[4*q+1] = v.y; ah[4*q+2] = v.z; ah[4*q+3] = v.w;
                }
                #pragma unroll
                for (int q = 0; q < 8; q++) {
                    uint4 v = __ldcg(sl + q);
                    al[4*q] = v.x; al[4*q+1] = v.y; al[4*q+2] = v.z; al[4*q+3] = v.w;
                }
                const int wrow = tid >> 2, qq = tid & 3;
                const size_t wbase = (((size_t)g * NLAYER + l) * HID + (n0 + wrow)) * HID + k0;
                const uint4* wh = (const uint4*)(g_w_hi + wbase);
                const uint4* wl = (const uint4*)(g_w_lo + wbase);
                #pragma unroll
                for (int e = 0; e < 2; e++) {
                    uint4 v = __ldg(wh + qq * 2 + e);
                    wreg[e*4] = v.x; wreg[e*4+1] = v.y; wreg[e*4+2] = v.z; wreg[e*4+3] = v.w;
                    v = __ldg(wl + qq * 2 + e);
                    wreg[8+e*4] = v.x; wreg[8+e*4+1] = v.y; wreg[8+e*4+2] = v.z; wreg[8+e*4+3] = v.w;
                }
            }

            // ---- recycle buffer b: MMAs of chunk ch-2 must be done ----
            if (ch >= 2) {
                if (b == 0) { MBAR_WAIT(mbar_a[0], u0 & 1); u0++; }
                else        { MBAR_WAIT(mbar_a[1], u1 & 1); u1++; }
                TC_FENCE_AFTER();
            }

            // ---- A -> TMEM (STTM), W -> SMEM (STS) ----
            const uint32_t acol = tmem + TM_A + (uint32_t)b * 128u + (uint32_t)half * 64u;
            STTM_X32(acol + warp_off, ah);
            STTM_X32(acol + 32u + warp_off, al);
            TC_WAIT_ST();
            {
                const int wrow = tid >> 2, qq = tid & 3;
                const uint32_t wb = smbase + (uint32_t)b * WBUFSZ;
                #pragma unroll
                for (int e = 0; e < 2; e++) {
                    uint32_t so = swz((uint32_t)wrow * 128u + (qq * 2 + e) * 16u);
                    sts128(wb + so,
                           make_uint4(wreg[e*4], wreg[e*4+1], wreg[e*4+2], wreg[e*4+3]));
                    sts128(wb + OFF_WLO + so,
                           make_uint4(wreg[8+e*4], wreg[8+e*4+1], wreg[8+e*4+2], wreg[8+e*4+3]));
                }
            }
            // Publish: STTM (tcgen05 proxy, cross-thread) + STS (generic -> async proxy)
            TC_FENCE_BEFORE();
            FENCE_ASYNC();
            __syncthreads();

            // ---- MMA issue: 2 M-halves x 3 passes x 4 k-steps (TS form) ----
            if (tid == 0) {
                TC_FENCE_AFTER();
                #pragma unroll
                for (int mh = 0; mh < 2; mh++) {
                    #pragma unroll
                    for (int ps = 0; ps < 3; ps++) {
                        // ps0: Ahi*Whi  ps1: Ahi*Wlo  ps2: Alo*Whi
                        uint32_t a0 = tmem + TM_A + (uint32_t)b * 128u
                                    + (uint32_t)mh * 64u + (ps == 2 ? 32u : 0u);
                        uint64_t bd = mkdesc(smbase + (uint32_t)b * WBUFSZ
                                             + (ps == 1 ? OFF_WLO : 0u));
                        #pragma unroll
                        for (int ks = 0; ks < 4; ks++) {
                            uint32_t en = !(ch == 0 && ps == 0 && ks == 0);
                            tc_mma_ts(tmem + TM_D + mh * 64, a0 + ks * 8,
                                      bd + ks * 2, IDESC, en);
                        }
                    }
                }
                tc_commit(mbar_a[b]);
            }
        }

        // drain both buffers
        MBAR_WAIT(mbar_a[0], u0 & 1); u0++;
        MBAR_WAIT(mbar_a[1], u1 & 1); u1++;
        TC_FENCE_AFTER();

        // ---- epilogue: LDTM -> +bias -> tanh -> split/store ----
        {
            const int mh  = wid >> 2;
            const int row = mh * 128 + (wid & 3) * 32 + lane;
            uint32_t r[64];
            LDTM_X32(r, tmem + TM_D + mh * 64);
            LDTM_X32(r + 32, tmem + TM_D + mh * 64 + 32);
            TC_WAIT_LD();

            float hv[64];
            #pragma unroll
            for (int c = 0; c < 64; c++)
                hv[c] = tanhf(__uint_as_float(r[c]) + bias_sm[c]);

            const int wp = s & 1;
            uint32_t hip[32], lop[32];
            #pragma unroll
            for (int c = 0; c < 64; c += 2)
                split2(hv[c], hv[c + 1], hip[c >> 1], lop[c >> 1]);
            uint4* dh = (uint4*)&g_h_hi[wp][l][row][n0];
            uint4* dl = (uint4*)&g_h_lo[wp][l][row][n0];
            #pragma unroll
            for (int q = 0; q < 8; q++) {
                dh[q] = make_uint4(hip[4*q], hip[4*q+1], hip[4*q+2], hip[4*q+3]);
                dl[q] = make_uint4(lop[4*q], lop[4*q+1], lop[4*q+2], lop[4*q+3]);
            }
            if (l == NLAYER - 1) {
                float4* yb = (float4*)(out + (size_t)t * BH + (size_t)row * HID + n0);
                #pragma unroll
                for (int q = 0; q < 16; q++)
                    yb[q] = make_float4(hv[4*q], hv[4*q+1], hv[4*q+2], hv[4*q+3]);
            }
            if (t == S_LEN - 1) {
                float4* hb = (float4*)(out + Y_ELEMS + (size_t)l * BH + (size_t)row * HID + n0);
                #pragma unroll
                for (int q = 0; q < 16; q++)
                    hb[q] = make_float4(hv[4*q], hv[4*q+1], hv[4*q+2], hv[4*q+3]);
            }
            TC_FENCE_BEFORE();
        }
    }

    __syncthreads();
    if (wid == 0) tc_dealloc(tmem, 512);

#else
    // ================= SIMT fp32x2 fallback (base sm_103 pass) =================
    extern __shared__ __align__(16) char dynsm[];
    float (*At)[FB_ASTR] = (float(*)[FB_ASTR])dynsm;
    float (*Wt)[FB_WSTR] = (float(*)[FB_WSTR])(dynsm + sizeof(float) * BATCH * FB_ASTR);

    const int tid = threadIdx.x;
    const int ty  = tid >> 2;
    const int tx  = tid & 3;
    const int l   = blockIdx.x / TPL;
    const int nb  = (blockIdx.x % TPL) * NT;

    const float* Wl_ih = Wih + (size_t)l * HID * HID;
    const float* Wl_hh = Whh + (size_t)l * HID * HID;

    for (int s = 0; s < S_LEN + NLAYER - 1; s++) {
        if (s > 0) grid_barrier();
        int t = s - l;
        if (t < 0 || t >= S_LEN) continue;

        const float* A0 = (l == 0) ? (x + (size_t)t * BH) : &g_hf[(s + 1) & 1][l - 1][0][0];
        const float* A1 = (t == 0) ? (h0 + (size_t)l * BH) : &g_hf[(s + 1) & 1][l][0][0];

        for (int st = 0; st < NT / 16; st++) {
            const int n0 = nb + st * 16;
            float bias[4];
            #pragma unroll
            for (int j = 0; j < 4; j++) {
                int c = n0 + tx * 4 + j;
                bias[j] = __ldg(&bih[l * HID + c]) + __ldg(&bhh[l * HID + c]);
            }
            unsigned long long acc[4][2];
            #pragma unroll
            for (int ri = 0; ri < 4; ri++) {
                acc[ri][0] = pack2(bias[0], bias[1]);
                acc[ri][1] = pack2(bias[2], bias[3]);
            }
            simt_gemm(A0, Wl_ih, n0, tid, ty, tx, acc, At, Wt);
            simt_gemm(A1, Wl_hh, n0, tid, ty, tx, acc, At, Wt);

            float* hb = &g_hf[s & 1][l][0][0];
            #pragma unroll
            for (int ri = 0; ri < 4; ri++) {
                float2 v0 = unpack2(acc[ri][0]);
                float2 v1 = unpack2(acc[ri][1]);
                float4 h;
                h.x = tanhf(v0.x); h.y = tanhf(v0.y);
                h.z = tanhf(v1.x); h.w = tanhf(v1.y);
                int row = ty + 64 * ri;
                size_t off = (size_t)row * HID + n0 + tx * 4;
                *(float4*)(hb + off) = h;
                if (l == NLAYER - 1)
                    *(float4*)(out + (size_t)t * BH + off) = h;
                if (t == S_LEN - 1)
                    *(float4*)(out + Y_ELEMS + (size_t)l * BH + off) = h;
            }
        }
    }
#endif
}

extern "C" void kernel_launch(void* const* d_in, const int* in_sizes, int n_in,
                              void* d_out, int out_size) {
    const float* x   = (const float*)d_in[0];
    const float* h0  = (const float*)d_in[1];
    const float* Wih = (const float*)d_in[2];
    const float* Whh = (const float*)d_in[3];
    const float* bih = (const float*)d_in[4];
    const float* bhh = (const float*)d_in[5];

    cudaFuncSetAttribute(rnn_tc, cudaFuncAttributeMaxDynamicSharedMemorySize, SMEM_DYN);

    size_t tot4 = (size_t)NLAYER * HID * HID / 4;
    split_weights<<<(unsigned)((tot4 + 255) / 256), 256>>>(Wih, Whh);
    split_x<<<4096, 256>>>(x);
    size_t h4 = (size_t)NLAYER * BH / 4;
    seed_h0<<<(unsigned)((h4 + 255) / 256), 256>>>(h0);
    rnn_tc<<<NCTA, NTHREADS, SMEM_DYN>>>(x, h0, Wih, Whh, bih, bhh, (float*)d_out);
}

// round 12
// speedup vs baseline: 1.7770x; 1.0922x over previous
#include <cuda_runtime.h>
#include <cuda_bf16.h>
#include <cstdint>
#include <cstddef>

// MinimalRNN 3-layer tanh RNN, S=256, B=256, H=1024.
// Persistent kernel, skewed layer pipeline (layer l computes t = s - l).
// sm_103a pass: tcgen05 bf16 3-pass (hi/lo split), TS mode (A in TMEM via
// STTM; W in SMEM). Base sm_103 pass: SIMT fp32x2 fallback.
// R12: prefetch with reduced risk vs R10/R11 (which failed the container
// twice, likely ptxas/register blowup): NBUF=2 (R9-proven accounting),
// #pragma unroll 1 chunk loop, epilogue processed in two 32-col halves to
// cut peak register pressure. Math identical to R9 (rel_err 1.67e-5).

#if defined(__CUDA_ARCH_FEAT_SM103_ALL) || defined(__CUDA_ARCH_FEAT_SM100_ALL) || \
    defined(__CUDA_ARCH_FEAT_SM101_ALL) || defined(__CUDA_ARCH_SPECIFIC__)
#define TC_OK 1
#endif
#if !defined(__CUDA_ARCH__) || defined(TC_OK)
#define COMPILE_TC 1          // host pass + arch-specific device pass
#endif

#define S_LEN   256
#define BATCH   256
#define HID     1024
#define NLAYER  3
#define NT      64
#define TPL     (HID / NT)          // 16
#define NCTA    (NLAYER * TPL)      // 48
#define NTHREADS 256
#define KC      64                  // k elems per chunk
#define NCHUNK  32                  // 2 GEMMs x 16 chunks (even)
#define NBUF    2                   // double buffer (proven in R9)
#define BH      ((size_t)BATCH * HID)
#define Y_ELEMS ((size_t)S_LEN * BATCH * HID)

// W stage buffers in SMEM: per buffer hi 8KB + lo 8KB
#define WBUFSZ  16384
#define OFF_WLO 8192
#define SMEM_DYN (NBUF * WBUFSZ + 1024)

// TMEM columns: D at 0 (128 cols), A buffers at 128 (2 x 128 cols)
#define TM_D    0
#define TM_A    128

// idesc kind::f16: dtype=F32(1<<4) atype=BF16(1<<7) btype=BF16(1<<10)
// N/8=8 (<<17), M/16=8 (<<24)
#define IDESC 0x08100490u

// ---------------- global scratch ----------------
__device__ __align__(16) __nv_bfloat16 g_w_hi[2u * NLAYER * HID * HID];
__device__ __align__(16) __nv_bfloat16 g_w_lo[2u * NLAYER * HID * HID];
__device__ __align__(16) __nv_bfloat16 g_x_hi[(size_t)S_LEN * BATCH * HID];
__device__ __align__(16) __nv_bfloat16 g_x_lo[(size_t)S_LEN * BATCH * HID];
__device__ __align__(16) __nv_bfloat16 g_h_hi[2][NLAYER][BATCH][HID];
__device__ __align__(16) __nv_bfloat16 g_h_lo[2][NLAYER][BATCH][HID];
__device__ __align__(16) float         g_hf[2][NLAYER][BATCH][HID];  // fallback
__device__ unsigned g_count = 0;
__device__ unsigned g_gen   = 0;

// ---------------- generic helpers ----------------
__device__ __forceinline__ uint32_t smem_u32(const void* p) {
    uint32_t a;
    asm("{ .reg .u64 t; cvta.to.shared.u64 t, %1; cvt.u32.u64 %0, t; }"
        : "=r"(a) : "l"(p));
    return a;
}
__device__ __forceinline__ uint32_t swz(uint32_t off) {   // SW128
    return off ^ ((off >> 3) & 0x70);
}
__device__ __forceinline__ void sts128(uint32_t addr, uint4 v) {
    asm volatile("st.shared.v4.b32 [%0], {%1,%2,%3,%4};"
                 :: "r"(addr), "r"(v.x), "r"(v.y), "r"(v.z), "r"(v.w) : "memory");
}
__device__ __forceinline__ uint64_t mkdesc(uint32_t addr) { // SW128, LBO=1, SBO=64
    return ((uint64_t)2 << 61) | ((uint64_t)1 << 46) | ((uint64_t)64 << 32)
         | ((uint64_t)1 << 16) | ((addr >> 4) & 0x3FFF);
}
__device__ __forceinline__ uint32_t pkbf(__nv_bfloat16 a, __nv_bfloat16 b) {
    __nv_bfloat162 t = __halves2bfloat162(a, b);
    return *reinterpret_cast<uint32_t*>(&t);
}
__device__ __forceinline__ void split2(float x, float y, uint32_t& h, uint32_t& l) {
    __nv_bfloat16 hx = __float2bfloat16(x), hy = __float2bfloat16(y);
    __nv_bfloat16 lx = __float2bfloat16(x - __bfloat162float(hx));
    __nv_bfloat16 ly = __float2bfloat16(y - __bfloat162float(hy));
    h = pkbf(hx, hy); l = pkbf(lx, ly);
}

// ---------------- grid barrier ----------------
__device__ __forceinline__ unsigned ld_acq(const unsigned* p) {
    unsigned v;
    asm volatile("ld.acquire.gpu.global.u32 %0, [%1];" : "=r"(v) : "l"(p) : "memory");
    return v;
}
__device__ __forceinline__ void grid_barrier() {
    __syncthreads();
    if (threadIdx.x == 0) {
        __threadfence();
        unsigned gen = ld_acq(&g_gen);
        __threadfence();
        unsigned ticket = atomicAdd(&g_count, 1u);
        if (ticket == NCTA - 1) {
            atomicExch(&g_count, 0u);
            __threadfence();
            atomicAdd(&g_gen, 1u);
        } else {
            while (ld_acq(&g_gen) == gen) { __nanosleep(64); }
        }
        __threadfence();
    }
    __syncthreads();
}

// ---------------- packed f32x2 (fallback path) ----------------
__device__ __forceinline__ void ffma2(unsigned long long& d,
                                      unsigned long long a, unsigned long long b) {
    asm volatile("fma.rn.f32x2 %0, %1, %2, %0;" : "+l"(d) : "l"(a), "l"(b));
}
__device__ __forceinline__ unsigned long long splat2(float v) {
    unsigned long long r;
    asm("mov.b64 %0, {%1, %1};" : "=l"(r) : "f"(v));
    return r;
}
__device__ __forceinline__ unsigned long long pack2(float a, float b) {
    unsigned long long r;
    asm("mov.b64 %0, {%1, %2};" : "=l"(r) : "f"(a), "f"(b));
    return r;
}
__device__ __forceinline__ float2 unpack2(unsigned long long v) {
    float2 f;
    asm("mov.b64 {%0, %1}, %2;" : "=f"(f.x), "=f"(f.y) : "l"(v));
    return f;
}

#define FB_KC   32
#define FB_ASTR 36
#define FB_WSTR 20
__device__ __forceinline__ void simt_gemm(
    const float* __restrict__ A, const float* __restrict__ W,
    int n0, int tid, int ty, int tx,
    unsigned long long acc[4][2],
    float (*At)[FB_ASTR], float (*Wt)[FB_WSTR])
{
    const int arow = tid >> 3, aq = tid & 7;
    const int wc = tid & 15, wq = tid >> 4;
    for (int kc = 0; kc < HID; kc += FB_KC) {
        #pragma unroll
        for (int it = 0; it < 8; it++) {
            int row = arow + 32 * it;
            float4 v = __ldcg((const float4*)(A + (size_t)row * HID + kc + aq * 4));
            *(float4*)&At[row][aq * 4] = v;
        }
        if (tid < 128) {
            float4 wv = __ldg((const float4*)(W + (size_t)(n0 + wc) * HID + kc + wq * 4));
            Wt[wq * 4 + 0][wc] = wv.x; Wt[wq * 4 + 1][wc] = wv.y;
            Wt[wq * 4 + 2][wc] = wv.z; Wt[wq * 4 + 3][wc] = wv.w;
        }
        __syncthreads();
        #pragma unroll
        for (int k4 = 0; k4 < FB_KC; k4 += 4) {
            ulonglong2 wp[4];
            #pragma unroll
            for (int j = 0; j < 4; j++)
                wp[j] = *(const ulonglong2*)&Wt[k4 + j][tx * 4];
            float4 av[4];
            #pragma unroll
            for (int ri = 0; ri < 4; ri++)
                av[ri] = *(const float4*)&At[ty + 64 * ri][k4];
            #pragma unroll
            for (int j = 0; j < 4; j++) {
                #pragma unroll
                for (int ri = 0; ri < 4; ri++) {
                    unsigned long long as = splat2(((const float*)&av[ri])[j]);
                    ffma2(acc[ri][0], as, wp[j].x);
                    ffma2(acc[ri][1], as, wp[j].y);
                }
            }
        }
        __syncthreads();
    }
}

// ---------------- tcgen05 wrappers (arch-specific pass only) ----------------
#if defined(COMPILE_TC)
#define MBARRIER_INIT(addr, cnt) \
    asm volatile("mbarrier.init.shared.b64 [%0], %1;" :: "r"(addr), "r"(cnt) : "memory")
#define MBAR_WAIT(addr, parity) do {                                            \
    uint32_t _done;                                                             \
    asm volatile("{\n\t.reg .pred p;\n\t"                                       \
        "mbarrier.try_wait.parity.acquire.cta.shared::cta.b64 p, [%1], %2;\n\t" \
        "selp.b32 %0, 1, 0, p;\n\t}"                                            \
        : "=r"(_done) : "r"(addr), "r"(parity) : "memory");                     \
    if (!_done) {                                                               \
        asm volatile("{\n\t.reg .pred P1;\n\t"                                  \
            "WL_%=:\n\t"                                                        \
            "mbarrier.try_wait.parity.acquire.cta.shared::cta.b64 P1, [%0], %1, 0x989680;\n\t" \
            "@P1 bra.uni WD_%=;\n\t"                                            \
            "bra.uni WL_%=;\n\t"                                                \
            "WD_%=:\n\t}" :: "r"(addr), "r"(parity) : "memory");                \
    }                                                                           \
} while (0)

__device__ __forceinline__ void tc_alloc(uint32_t dst_smem, uint32_t ncols) {
    asm volatile("tcgen05.alloc.cta_group::1.sync.aligned.shared::cta.b32 [%0], %1;"
                 :: "r"(dst_smem), "r"(ncols) : "memory");
}
__device__ __forceinline__ void tc_dealloc(uint32_t tmem, uint32_t ncols) {
    asm volatile("tcgen05.dealloc.cta_group::1.sync.aligned.b32 %0, %1;"
                 :: "r"(tmem), "r"(ncols));
}
__device__ __forceinline__ void tc_relinquish() {
    asm volatile("tcgen05.relinquish_alloc_permit.cta_group::1.sync.aligned;");
}
// TS form: A operand in TMEM
__device__ __forceinline__ void tc_mma_ts(uint32_t d, uint32_t a, uint64_t bd,
                                          uint32_t idesc, uint32_t en) {
    asm volatile("{\n\t.reg .pred p;\n\tsetp.ne.u32 p, %5, 0;\n\t"
        "tcgen05.mma.cta_group::1.kind::f16 [%0], [%1], %2, %3, {%4,%4,%4,%4}, p;\n\t}"
        :: "r"(d), "r"(a), "l"(bd), "r"(idesc), "r"(0u), "r"(en) : "memory");
}
__device__ __forceinline__ void tc_commit(uint32_t mbar) {
    asm volatile("tcgen05.commit.cta_group::1.mbarrier::arrive::one.shared::cluster.b64 [%0];"
                 :: "r"(mbar) : "memory");
}
#define TC_FENCE_BEFORE() asm volatile("tcgen05.fence::before_thread_sync;" ::: "memory")
#define TC_FENCE_AFTER()  asm volatile("tcgen05.fence::after_thread_sync;"  ::: "memory")
#define TC_WAIT_LD()      asm volatile("tcgen05.wait::ld.sync.aligned;" ::: "memory")
#define TC_WAIT_ST()      asm volatile("tcgen05.wait::st.sync.aligned;" ::: "memory")
#define FENCE_ASYNC()     asm volatile("fence.proxy.async.shared::cta;" ::: "memory")

#define LDTM_X32(r, a)                                                          \
    asm volatile("tcgen05.ld.sync.aligned.32x32b.x32.b32 "                      \
        "{%0,%1,%2,%3,%4,%5,%6,%7,%8,%9,%10,%11,%12,%13,%14,%15,"               \
        "%16,%17,%18,%19,%20,%21,%22,%23,%24,%25,%26,%27,%28,%29,%30,%31}, [%32];" \
        : "=r"((r)[0]),"=r"((r)[1]),"=r"((r)[2]),"=r"((r)[3]),                  \
          "=r"((r)[4]),"=r"((r)[5]),"=r"((r)[6]),"=r"((r)[7]),                  \
          "=r"((r)[8]),"=r"((r)[9]),"=r"((r)[10]),"=r"((r)[11]),                \
          "=r"((r)[12]),"=r"((r)[13]),"=r"((r)[14]),"=r"((r)[15]),              \
          "=r"((r)[16]),"=r"((r)[17]),"=r"((r)[18]),"=r"((r)[19]),              \
          "=r"((r)[20]),"=r"((r)[21]),"=r"((r)[22]),"=r"((r)[23]),              \
          "=r"((r)[24]),"=r"((r)[25]),"=r"((r)[26]),"=r"((r)[27]),              \
          "=r"((r)[28]),"=r"((r)[29]),"=r"((r)[30]),"=r"((r)[31])               \
        : "r"(a))

#define STTM_X32(a, r)                                                          \
    asm volatile("tcgen05.st.sync.aligned.32x32b.x32.b32 [%0], "                \
        "{%1,%2,%3,%4,%5,%6,%7,%8,%9,%10,%11,%12,%13,%14,%15,%16,"              \
        "%17,%18,%19,%20,%21,%22,%23,%24,%25,%26,%27,%28,%29,%30,%31,%32};"     \
        :: "r"(a),                                                              \
           "r"((r)[0]),"r"((r)[1]),"r"((r)[2]),"r"((r)[3]),                     \
           "r"((r)[4]),"r"((r)[5]),"r"((r)[6]),"r"((r)[7]),                     \
           "r"((r)[8]),"r"((r)[9]),"r"((r)[10]),"r"((r)[11]),                   \
           "r"((r)[12]),"r"((r)[13]),"r"((r)[14]),"r"((r)[15]),                 \
           "r"((r)[16]),"r"((r)[17]),"r"((r)[18]),"r"((r)[19]),                 \
           "r"((r)[20]),"r"((r)[21]),"r"((r)[22]),"r"((r)[23]),                 \
           "r"((r)[24]),"r"((r)[25]),"r"((r)[26]),"r"((r)[27]),                 \
           "r"((r)[28]),"r"((r)[29]),"r"((r)[30]),"r"((r)[31])                  \
        : "memory")
#endif // COMPILE_TC

// ---------------- prelude kernels ----------------
extern "C" __global__ void split_weights(const float* __restrict__ Wih,
                                         const float* __restrict__ Whh) {
    size_t tot4 = (size_t)NLAYER * HID * HID / 4;
    size_t i4 = (size_t)blockIdx.x * blockDim.x + threadIdx.x;
    if (i4 >= tot4) return;
    float4 a = __ldg((const float4*)Wih + i4);
    float4 b = __ldg((const float4*)Whh + i4);
    uint2 h, l;
    split2(a.x, a.y, h.x, l.x); split2(a.z, a.w, h.y, l.y);
    ((uint2*)g_w_hi)[i4] = h;  ((uint2*)g_w_lo)[i4] = l;
    split2(b.x, b.y, h.x, l.x); split2(b.z, b.w, h.y, l.y);
    ((uint2*)g_w_hi)[tot4 + i4] = h;  ((uint2*)g_w_lo)[tot4 + i4] = l;
}

extern "C" __global__ void split_x(const float* __restrict__ x) {
    size_t tot4 = Y_ELEMS / 4;
    for (size_t i4 = (size_t)blockIdx.x * blockDim.x + threadIdx.x;
         i4 < tot4; i4 += (size_t)gridDim.x * blockDim.x) {
        float4 a = __ldg((const float4*)x + i4);
        uint2 h, l;
        split2(a.x, a.y, h.x, l.x); split2(a.z, a.w, h.y, l.y);
        ((uint2*)g_x_hi)[i4] = h;  ((uint2*)g_x_lo)[i4] = l;
    }
}

// seed h0 into the parity slot read at t==0 for each layer: pp = (l+1)&1
extern "C" __global__ void seed_h0(const float* __restrict__ h0) {
    size_t tot4 = (size_t)NLAYER * BH / 4;
    size_t i4 = (size_t)blockIdx.x * blockDim.x + threadIdx.x;
    if (i4 >= tot4) return;
    int l = (int)(i4 / (BH / 4));
    size_t r4 = i4 % (BH / 4);
    int pp = (l + 1) & 1;
    float4 a = __ldg((const float4*)h0 + i4);
    uint2 h, lo;
    split2(a.x, a.y, h.x, lo.x); split2(a.z, a.w, h.y, lo.y);
    ((uint2*)&g_h_hi[pp][l][0][0])[r4] = h;
    ((uint2*)&g_h_lo[pp][l][0][0])[r4] = lo;
}

#if defined(COMPILE_TC)
// ---------------- chunk load (registers) ----------------
__device__ __forceinline__ void loadc(
    int ch, int tid, int l, int n0,
    const __nv_bfloat16* a0h, const __nv_bfloat16* a0l,
    const __nv_bfloat16* a1h, const __nv_bfloat16* a1l,
    uint32_t* ah, uint32_t* al, uint32_t* wreg)
{
    const int g  = ch >> 4;
    const int k0 = (ch & 15) * KC;
    const size_t aoff = (size_t)tid * HID + k0;
    const uint4* sh = (const uint4*)((g ? a1h : a0h) + aoff);
    const uint4* sl = (const uint4*)((g ? a1l : a0l) + aoff);
    #pragma unroll
    for (int q = 0; q < 8; q++) {
        uint4 v = __ldcg(sh + q);
        ah[4*q] = v.x; ah[4*q+1] = v.y; ah[4*q+2] = v.z; ah[4*q+3] = v.w;
    }
    #pragma unroll
    for (int q = 0; q < 8; q++) {
        uint4 v = __ldcg(sl + q);
        al[4*q] = v.x; al[4*q+1] = v.y; al[4*q+2] = v.z; al[4*q+3] = v.w;
    }
    const int wrow = tid >> 2, qq = tid & 3;
    const size_t wbase = (((size_t)g * NLAYER + l) * HID + (n0 + wrow)) * HID + k0;
    const uint4* wh = (const uint4*)(g_w_hi + wbase);
    const uint4* wl = (const uint4*)(g_w_lo + wbase);
    #pragma unroll
    for (int e = 0; e < 2; e++) {
        uint4 v = __ldg(wh + qq * 2 + e);
        wreg[e*4] = v.x; wreg[e*4+1] = v.y; wreg[e*4+2] = v.z; wreg[e*4+3] = v.w;
        v = __ldg(wl + qq * 2 + e);
        wreg[8+e*4] = v.x; wreg[8+e*4+1] = v.y; wreg[8+e*4+2] = v.z; wreg[8+e*4+3] = v.w;
    }
}

// ---------------- chunk stage + MMA issue (NBUF=2, R9 accounting) ----------
__device__ __forceinline__ void stagec(
    int ch, int tid, uint32_t tmem, uint32_t smbase, uint32_t mb0,
    unsigned& u0, unsigned& u1,
    uint32_t warp_off, int half,
    const uint32_t* ah, const uint32_t* al, const uint32_t* wreg)
{
    const int b = ch & 1;
    const uint32_t mbar = mb0 + (uint32_t)b * 8u;
    if (ch >= NBUF) {
        if (b == 0) { MBAR_WAIT(mbar, u0 & 1); u0++; }
        else        { MBAR_WAIT(mbar, u1 & 1); u1++; }
        TC_FENCE_AFTER();
    }
    // A -> TMEM
    const uint32_t acol = tmem + TM_A + (uint32_t)b * 128u + (uint32_t)half * 64u;
    STTM_X32(acol + warp_off, ah);
    STTM_X32(acol + 32u + warp_off, al);
    TC_WAIT_ST();
    // W -> SMEM
    {
        const int wrow = tid >> 2, qq = tid & 3;
        const uint32_t wb = smbase + (uint32_t)b * WBUFSZ;
        #pragma unroll
        for (int e = 0; e < 2; e++) {
            uint32_t so = swz((uint32_t)wrow * 128u + (qq * 2 + e) * 16u);
            sts128(wb + so,
                   make_uint4(wreg[e*4], wreg[e*4+1], wreg[e*4+2], wreg[e*4+3]));
            sts128(wb + OFF_WLO + so,
                   make_uint4(wreg[8+e*4], wreg[8+e*4+1], wreg[8+e*4+2], wreg[8+e*4+3]));
        }
    }
    // Publish: STTM (tcgen05 proxy, cross-thread) + STS (generic -> async proxy)
    TC_FENCE_BEFORE();
    FENCE_ASYNC();
    __syncthreads();

    if (tid == 0) {
        TC_FENCE_AFTER();
        #pragma unroll
        for (int mh = 0; mh < 2; mh++) {
            #pragma unroll
            for (int ps = 0; ps < 3; ps++) {
                // ps0: Ahi*Whi  ps1: Ahi*Wlo  ps2: Alo*Whi
                uint32_t a0 = tmem + TM_A + (uint32_t)b * 128u
                            + (uint32_t)mh * 64u + (ps == 2 ? 32u : 0u);
                uint64_t bd = mkdesc(smbase + (uint32_t)b * WBUFSZ
                                     + (ps == 1 ? OFF_WLO : 0u));
                #pragma unroll
                for (int ks = 0; ks < 4; ks++) {
                    uint32_t en = !(ch == 0 && ps == 0 && ks == 0);
                    tc_mma_ts(tmem + TM_D + mh * 64, a0 + ks * 8,
                              bd + ks * 2, IDESC, en);
                }
            }
        }
        tc_commit(mbar);
    }
}
#endif // COMPILE_TC

// ---------------- persistent RNN kernel ----------------
extern "C" __global__ void __launch_bounds__(NTHREADS, 1)
rnn_tc(const float* __restrict__ x,    // [S][B][H]
       const float* __restrict__ h0,   // [L][B][H]
       const float* __restrict__ Wih,  // fallback path only
       const float* __restrict__ Whh,  // fallback path only
       const float* __restrict__ bih,  // [L][H]
       const float* __restrict__ bhh,  // [L][H]
       float* __restrict__ out)        // y [S*B*H] ++ h_N [L*B*H]
{
#if defined(COMPILE_TC)
    // ================= tcgen05 TS-mode 3-pass path =================
    (void)x; (void)h0; (void)Wih; (void)Whh;
    extern __shared__ __align__(1024) char dynsm[];
    __shared__ __align__(16) uint64_t mbar[NBUF];
    __shared__ uint32_t tmem_ptr_sm;
    __shared__ float bias_sm[NT];

    const int tid  = threadIdx.x;
    const int wid  = tid >> 5;
    const int lane = tid & 31;
    const int l    = blockIdx.x / TPL;
    const int n0   = (blockIdx.x % TPL) * NT;
    const uint32_t warp_off = (uint32_t)(wid & 3) << 21;  // TMEM subpartition
    const int half = tid >> 7;                            // M-half of my A row

    uint32_t smbase = smem_u32(dynsm);
    smbase = (smbase + 1023u) & ~1023u;
    const uint32_t mb0 = smem_u32(&mbar[0]);

    if (wid == 0) tc_alloc(smem_u32(&tmem_ptr_sm), 512);
    if (tid == 0) {
        MBARRIER_INIT(mb0 + 0, 1);
        MBARRIER_INIT(mb0 + 8, 1);
    }
    if (tid < NT)
        bias_sm[tid] = __ldg(&bih[l * HID + n0 + tid]) + __ldg(&bhh[l * HID + n0 + tid]);
    __syncthreads();
    const uint32_t tmem = tmem_ptr_sm;
    if (wid == 0) tc_relinquish();

    unsigned u0 = 0, u1 = 0;

    for (int s = 0; s < S_LEN + NLAYER - 1; s++) {
        if (s > 0) grid_barrier();
        const int t = s - l;
        if (t < 0 || t >= S_LEN) continue;
        const int pp = (s + 1) & 1;

        // A sources (all pre-split bf16)
        const __nv_bfloat16* a0h = (l == 0) ? (g_x_hi + (size_t)t * BH)
                                            : &g_h_hi[pp][l - 1][0][0];
        const __nv_bfloat16* a0l = (l == 0) ? (g_x_lo + (size_t)t * BH)
                                            : &g_h_lo[pp][l - 1][0][0];
        const __nv_bfloat16* a1h = &g_h_hi[pp][l][0][0];
        const __nv_bfloat16* a1l = &g_h_lo[pp][l][0][0];

        // Software pipeline: loads for chunk ch+1 are issued before chunk ch
        // is staged, hiding global latency behind staging/MMA.
        uint32_t ahA[32], alA[32], wA[16];
        uint32_t ahB[32], alB[32], wB[16];

        loadc(0, tid, l, n0, a0h, a0l, a1h, a1l, ahA, alA, wA);
        #pragma unroll 1
        for (int ch = 0; ch < NCHUNK; ch += 2) {
            loadc(ch + 1, tid, l, n0, a0h, a0l, a1h, a1l, ahB, alB, wB);
            stagec(ch, tid, tmem, smbase, mb0, u0, u1, warp_off, half,
                   ahA, alA, wA);
            if (ch + 2 < NCHUNK)
                loadc(ch + 2, tid, l, n0, a0h, a0l, a1h, a1l, ahA, alA, wA);
            stagec(ch + 1, tid, tmem, smbase, mb0, u0, u1, warp_off, half,
                   ahB, alB, wB);
        }

        // drain: each buffer has exactly one outstanding commit (chunks 30/31)
        MBAR_WAIT(mb0 + 0, u0 & 1); u0++;
        MBAR_WAIT(mb0 + 8, u1 & 1); u1++;
        TC_FENCE_AFTER();

        // ---- epilogue: LDTM -> +bias -> tanh -> split/store ----
        // Processed in two 32-column halves to cap register pressure.
        {
            const int mh  = wid >> 2;
            const int row = mh * 128 + (wid & 3) * 32 + lane;
            const int wp  = s & 1;

            #pragma unroll
            for (int hf = 0; hf < 2; hf++) {
                uint32_t r[32];
                LDTM_X32(r, tmem + TM_D + mh * 64 + hf * 32);
                TC_WAIT_LD();

                float hv[32];
                #pragma unroll
                for (int c = 0; c < 32; c++)
                    hv[c] = tanhf(__uint_as_float(r[c]) + bias_sm[hf * 32 + c]);

                uint32_t hip[16], lop[16];
                #pragma unroll
                for (int c = 0; c < 32; c += 2)
                    split2(hv[c], hv[c + 1], hip[c >> 1], lop[c >> 1]);

                uint4* dh = (uint4*)&g_h_hi[wp][l][row][n0 + hf * 32];
                uint4* dl = (uint4*)&g_h_lo[wp][l][row][n0 + hf * 32];
                #pragma unroll
                for (int q = 0; q < 4; q++) {
                    dh[q] = make_uint4(hip[4*q], hip[4*q+1], hip[4*q+2], hip[4*q+3]);
                    dl[q] = make_uint4(lop[4*q], lop[4*q+1], lop[4*q+2], lop[4*q+3]);
                }
                if (l == NLAYER - 1) {
                    float4* yb = (float4*)(out + (size_t)t * BH
                                           + (size_t)row * HID + n0 + hf * 32);
                    #pragma unroll
                    for (int q = 0; q < 8; q++)
                        yb[q] = make_float4(hv[4*q], hv[4*q+1], hv[4*q+2], hv[4*q+3]);
                }
                if (t == S_LEN - 1) {
                    float4* hb = (float4*)(out + Y_ELEMS + (size_t)l * BH
                                           + (size_t)row * HID + n0 + hf * 32);
                    #pragma unroll
                    for (int q = 0; q < 8; q++)
                        hb[q] = make_float4(hv[4*q], hv[4*q+1], hv[4*q+2], hv[4*q+3]);
                }
            }
            TC_FENCE_BEFORE();
        }
    }

    __syncthreads();
    if (wid == 0) tc_dealloc(tmem, 512);

#else
    // ================= SIMT fp32x2 fallback (base sm_103 pass) =================
    extern __shared__ __align__(16) char dynsm[];
    float (*At)[FB_ASTR] = (float(*)[FB_ASTR])dynsm;
    float (*Wt)[FB_WSTR] = (float(*)[FB_WSTR])(dynsm + sizeof(float) * BATCH * FB_ASTR);

    const int tid = threadIdx.x;
    const int ty  = tid >> 2;
    const int tx  = tid & 3;
    const int l   = blockIdx.x / TPL;
    const int nb  = (blockIdx.x % TPL) * NT;

    const float* Wl_ih = Wih + (size_t)l * HID * HID;
    const float* Wl_hh = Whh + (size_t)l * HID * HID;

    for (int s = 0; s < S_LEN + NLAYER - 1; s++) {
        if (s > 0) grid_barrier();
        int t = s - l;
        if (t < 0 || t >= S_LEN) continue;

        const float* A0 = (l == 0) ? (x + (size_t)t * BH) : &g_hf[(s + 1) & 1][l - 1][0][0];
        const float* A1 = (t == 0) ? (h0 + (size_t)l * BH) : &g_hf[(s + 1) & 1][l][0][0];

        for (int st = 0; st < NT / 16; st++) {
            const int n0 = nb + st * 16;
            float bias[4];
            #pragma unroll
            for (int j = 0; j < 4; j++) {
                int c = n0 + tx * 4 + j;
                bias[j] = __ldg(&bih[l * HID + c]) + __ldg(&bhh[l * HID + c]);
            }
            unsigned long long acc[4][2];
            #pragma unroll
            for (int ri = 0; ri < 4; ri++) {
                acc[ri][0] = pack2(bias[0], bias[1]);
                acc[ri][1] = pack2(bias[2], bias[3]);
            }
            simt_gemm(A0, Wl_ih, n0, tid, ty, tx, acc, At, Wt);
            simt_gemm(A1, Wl_hh, n0, tid, ty, tx, acc, At, Wt);

            float* hb = &g_hf[s & 1][l][0][0];
            #pragma unroll
            for (int ri = 0; ri < 4; ri++) {
                float2 v0 = unpack2(acc[ri][0]);
                float2 v1 = unpack2(acc[ri][1]);
                float4 h;
                h.x = tanhf(v0.x); h.y = tanhf(v0.y);
                h.z = tanhf(v1.x); h.w = tanhf(v1.y);
                int row = ty + 64 * ri;
                size_t off = (size_t)row * HID + n0 + tx * 4;
                *(float4*)(hb + off) = h;
                if (l == NLAYER - 1)
                    *(float4*)(out + (size_t)t * BH + off) = h;
                if (t == S_LEN - 1)
                    *(float4*)(out + Y_ELEMS + (size_t)l * BH + off) = h;
            }
        }
    }
#endif
}

extern "C" void kernel_launch(void* const* d_in, const int* in_sizes, int n_in,
                              void* d_out, int out_size) {
    const float* x   = (const float*)d_in[0];
    const float* h0  = (const float*)d_in[1];
    const float* Wih = (const float*)d_in[2];
    const float* Whh = (const float*)d_in[3];
    const float* bih = (const float*)d_in[4];
    const float* bhh = (const float*)d_in[5];

    cudaFuncSetAttribute(rnn_tc, cudaFuncAttributeMaxDynamicSharedMemorySize, SMEM_DYN);

    size_t tot4 = (size_t)NLAYER * HID * HID / 4;
    split_weights<<<(unsigned)((tot4 + 255) / 256), 256>>>(Wih, Whh);
    split_x<<<4096, 256>>>(x);
    size_t h4 = (size_t)NLAYER * BH / 4;
    seed_h0<<<(unsigned)((h4 + 255) / 256), 256>>>(h0);
    rnn_tc<<<NCTA, NTHREADS, SMEM_DYN>>>(x, h0, Wih, Whh, bih, bhh, (float*)d_out);
}

// round 13
// speedup vs baseline: 1.8967x; 1.0674x over previous
#include <cuda_runtime.h>
#include <cuda_bf16.h>
#include <cstdint>
#include <cstddef>

// MinimalRNN 3-layer tanh RNN, S=256, B=256, H=1024.
// Persistent kernel, skewed layer pipeline (layer l computes t = s - l).
// sm_103a pass: tcgen05 bf16 3-pass (hi/lo split), TS mode (A in TMEM via
// STTM; W in SMEM). Base sm_103 pass: SIMT fp32x2 fallback.
// R13: R12 hit the 255-reg cap (two 80-reg prefetch sets spilled, defeating
// prefetch). Now: W staged via cp.async (no registers, async, 4-buf ring),
// A prefetch reduced to ONE register set (freed by TC_WAIT_ST before the
// next chunk's loads issue). Math identical (rel_err 1.67e-5).

#if defined(__CUDA_ARCH_FEAT_SM103_ALL) || defined(__CUDA_ARCH_FEAT_SM100_ALL) || \
    defined(__CUDA_ARCH_FEAT_SM101_ALL) || defined(__CUDA_ARCH_SPECIFIC__)
#define TC_OK 1
#endif
#if !defined(__CUDA_ARCH__) || defined(TC_OK)
#define COMPILE_TC 1          // host pass + arch-specific device pass
#endif

#define S_LEN   256
#define BATCH   256
#define HID     1024
#define NLAYER  3
#define NT      64
#define TPL     (HID / NT)          // 16
#define NCTA    (NLAYER * TPL)      // 48
#define NTHREADS 256
#define KC      64                  // k elems per chunk
#define NCHUNK  32                  // 2 GEMMs x 16 chunks
#define BH      ((size_t)BATCH * HID)
#define Y_ELEMS ((size_t)S_LEN * BATCH * HID)

// W stage: 4-deep ring in SMEM, per buffer hi 8KB + lo 8KB
#define WBUFSZ  16384
#define OFF_WLO 8192
#define NWBUF   4
#define SMEM_DYN (NWBUF * WBUFSZ + 1024)

// TMEM columns: D at 0 (128 cols), A buffers at 128 (2 x 128 cols)
#define TM_D    0
#define TM_A    128

// idesc kind::f16: dtype=F32(1<<4) atype=BF16(1<<7) btype=BF16(1<<10)
// N/8=8 (<<17), M/16=8 (<<24)
#define IDESC 0x08100490u

// ---------------- global scratch ----------------
__device__ __align__(16) __nv_bfloat16 g_w_hi[2u * NLAYER * HID * HID];
__device__ __align__(16) __nv_bfloat16 g_w_lo[2u * NLAYER * HID * HID];
__device__ __align__(16) __nv_bfloat16 g_x_hi[(size_t)S_LEN * BATCH * HID];
__device__ __align__(16) __nv_bfloat16 g_x_lo[(size_t)S_LEN * BATCH * HID];
__device__ __align__(16) __nv_bfloat16 g_h_hi[2][NLAYER][BATCH][HID];
__device__ __align__(16) __nv_bfloat16 g_h_lo[2][NLAYER][BATCH][HID];
__device__ __align__(16) float         g_hf[2][NLAYER][BATCH][HID];  // fallback
__device__ unsigned g_count = 0;
__device__ unsigned g_gen   = 0;

// ---------------- generic helpers ----------------
__device__ __forceinline__ uint32_t smem_u32(const void* p) {
    uint32_t a;
    asm("{ .reg .u64 t; cvta.to.shared.u64 t, %1; cvt.u32.u64 %0, t; }"
        : "=r"(a) : "l"(p));
    return a;
}
__device__ __forceinline__ uint32_t swz(uint32_t off) {   // SW128
    return off ^ ((off >> 3) & 0x70);
}
__device__ __forceinline__ uint64_t mkdesc(uint32_t addr) { // SW128, LBO=1, SBO=64
    return ((uint64_t)2 << 61) | ((uint64_t)1 << 46) | ((uint64_t)64 << 32)
         | ((uint64_t)1 << 16) | ((addr >> 4) & 0x3FFF);
}
__device__ __forceinline__ uint32_t pkbf(__nv_bfloat16 a, __nv_bfloat16 b) {
    __nv_bfloat162 t = __halves2bfloat162(a, b);
    return *reinterpret_cast<uint32_t*>(&t);
}
__device__ __forceinline__ void split2(float x, float y, uint32_t& h, uint32_t& l) {
    __nv_bfloat16 hx = __float2bfloat16(x), hy = __float2bfloat16(y);
    __nv_bfloat16 lx = __float2bfloat16(x - __bfloat162float(hx));
    __nv_bfloat16 ly = __float2bfloat16(y - __bfloat162float(hy));
    h = pkbf(hx, hy); l = pkbf(lx, ly);
}

// ---------------- grid barrier ----------------
__device__ __forceinline__ unsigned ld_acq(const unsigned* p) {
    unsigned v;
    asm volatile("ld.acquire.gpu.global.u32 %0, [%1];" : "=r"(v) : "l"(p) : "memory");
    return v;
}
__device__ __forceinline__ void grid_barrier() {
    __syncthreads();
    if (threadIdx.x == 0) {
        __threadfence();
        unsigned gen = ld_acq(&g_gen);
        __threadfence();
        unsigned ticket = atomicAdd(&g_count, 1u);
        if (ticket == NCTA - 1) {
            atomicExch(&g_count, 0u);
            __threadfence();
            atomicAdd(&g_gen, 1u);
        } else {
            while (ld_acq(&g_gen) == gen) { __nanosleep(64); }
        }
        __threadfence();
    }
    __syncthreads();
}

// ---------------- packed f32x2 (fallback path) ----------------
__device__ __forceinline__ void ffma2(unsigned long long& d,
                                      unsigned long long a, unsigned long long b) {
    asm volatile("fma.rn.f32x2 %0, %1, %2, %0;" : "+l"(d) : "l"(a), "l"(b));
}
__device__ __forceinline__ unsigned long long splat2(float v) {
    unsigned long long r;
    asm("mov.b64 %0, {%1, %1};" : "=l"(r) : "f"(v));
    return r;
}
__device__ __forceinline__ unsigned long long pack2(float a, float b) {
    unsigned long long r;
    asm("mov.b64 %0, {%1, %2};" : "=l"(r) : "f"(a), "f"(b));
    return r;
}
__device__ __forceinline__ float2 unpack2(unsigned long long v) {
    float2 f;
    asm("mov.b64 {%0, %1}, %2;" : "=f"(f.x), "=f"(f.y) : "l"(v));
    return f;
}

#define FB_KC   32
#define FB_ASTR 36
#define FB_WSTR 20
__device__ __forceinline__ void simt_gemm(
    const float* __restrict__ A, const float* __restrict__ W,
    int n0, int tid, int ty, int tx,
    unsigned long long acc[4][2],
    float (*At)[FB_ASTR], float (*Wt)[FB_WSTR])
{
    const int arow = tid >> 3, aq = tid & 7;
    const int wc = tid & 15, wq = tid >> 4;
    for (int kc = 0; kc < HID; kc += FB_KC) {
        #pragma unroll
        for (int it = 0; it < 8; it++) {
            int row = arow + 32 * it;
            float4 v = __ldcg((const float4*)(A + (size_t)row * HID + kc + aq * 4));
            *(float4*)&At[row][aq * 4] = v;
        }
        if (tid < 128) {
            float4 wv = __ldg((const float4*)(W + (size_t)(n0 + wc) * HID + kc + wq * 4));
            Wt[wq * 4 + 0][wc] = wv.x; Wt[wq * 4 + 1][wc] = wv.y;
            Wt[wq * 4 + 2][wc] = wv.z; Wt[wq * 4 + 3][wc] = wv.w;
        }
        __syncthreads();
        #pragma unroll
        for (int k4 = 0; k4 < FB_KC; k4 += 4) {
            ulonglong2 wp[4];
            #pragma unroll
            for (int j = 0; j < 4; j++)
                wp[j] = *(const ulonglong2*)&Wt[k4 + j][tx * 4];
            float4 av[4];
            #pragma unroll
            for (int ri = 0; ri < 4; ri++)
                av[ri] = *(const float4*)&At[ty + 64 * ri][k4];
            #pragma unroll
            for (int j = 0; j < 4; j++) {
                #pragma unroll
                for (int ri = 0; ri < 4; ri++) {
                    unsigned long long as = splat2(((const float*)&av[ri])[j]);
                    ffma2(acc[ri][0], as, wp[j].x);
                    ffma2(acc[ri][1], as, wp[j].y);
                }
            }
        }
        __syncthreads();
    }
}

// ---------------- tcgen05 / async wrappers (arch-specific pass only) --------
#if defined(COMPILE_TC)
#define MBARRIER_INIT(addr, cnt) \
    asm volatile("mbarrier.init.shared.b64 [%0], %1;" :: "r"(addr), "r"(cnt) : "memory")
#define MBAR_WAIT(addr, parity) do {                                            \
    uint32_t _done;                                                             \
    asm volatile("{\n\t.reg .pred p;\n\t"                                       \
        "mbarrier.try_wait.parity.acquire.cta.shared::cta.b64 p, [%1], %2;\n\t" \
        "selp.b32 %0, 1, 0, p;\n\t}"                                            \
        : "=r"(_done) : "r"(addr), "r"(parity) : "memory");                     \
    if (!_done) {                                                               \
        asm volatile("{\n\t.reg .pred P1;\n\t"                                  \
            "WL_%=:\n\t"                                                        \
            "mbarrier.try_wait.parity.acquire.cta.shared::cta.b64 P1, [%0], %1, 0x989680;\n\t" \
            "@P1 bra.uni WD_%=;\n\t"                                            \
            "bra.uni WL_%=;\n\t"                                                \
            "WD_%=:\n\t}" :: "r"(addr), "r"(parity) : "memory");                \
    }                                                                           \
} while (0)

__device__ __forceinline__ void tc_alloc(uint32_t dst_smem, uint32_t ncols) {
    asm volatile("tcgen05.alloc.cta_group::1.sync.aligned.shared::cta.b32 [%0], %1;"
                 :: "r"(dst_smem), "r"(ncols) : "memory");
}
__device__ __forceinline__ void tc_dealloc(uint32_t tmem, uint32_t ncols) {
    asm volatile("tcgen05.dealloc.cta_group::1.sync.aligned.b32 %0, %1;"
                 :: "r"(tmem), "r"(ncols));
}
__device__ __forceinline__ void tc_relinquish() {
    asm volatile("tcgen05.relinquish_alloc_permit.cta_group::1.sync.aligned;");
}
// TS form: A operand in TMEM
__device__ __forceinline__ void tc_mma_ts(uint32_t d, uint32_t a, uint64_t bd,
                                          uint32_t idesc, uint32_t en) {
    asm volatile("{\n\t.reg .pred p;\n\tsetp.ne.u32 p, %5, 0;\n\t"
        "tcgen05.mma.cta_group::1.kind::f16 [%0], [%1], %2, %3, {%4,%4,%4,%4}, p;\n\t}"
        :: "r"(d), "r"(a), "l"(bd), "r"(idesc), "r"(0u), "r"(en) : "memory");
}
__device__ __forceinline__ void tc_commit(uint32_t mbar) {
    asm volatile("tcgen05.commit.cta_group::1.mbarrier::arrive::one.shared::cluster.b64 [%0];"
                 :: "r"(mbar) : "memory");
}
#define TC_FENCE_BEFORE() asm volatile("tcgen05.fence::before_thread_sync;" ::: "memory")
#define TC_FENCE_AFTER()  asm volatile("tcgen05.fence::after_thread_sync;"  ::: "memory")
#define TC_WAIT_LD()      asm volatile("tcgen05.wait::ld.sync.aligned;" ::: "memory")
#define TC_WAIT_ST()      asm volatile("tcgen05.wait::st.sync.aligned;" ::: "memory")
#define FENCE_ASYNC()     asm volatile("fence.proxy.async.shared::cta;" ::: "memory")

// cp.async 16B global->shared (LDGSTS), bypasses registers
__device__ __forceinline__ void cp16(uint32_t dst, const void* src) {
    asm volatile("cp.async.cg.shared.global [%0], [%1], 16;"
                 :: "r"(dst), "l"(src) : "memory");
}
#define CP_COMMIT() asm volatile("cp.async.commit_group;" ::: "memory")
#define CP_WAIT2()  asm volatile("cp.async.wait_group 2;" ::: "memory")

#define LDTM_X32(r, a)                                                          \
    asm volatile("tcgen05.ld.sync.aligned.32x32b.x32.b32 "                      \
        "{%0,%1,%2,%3,%4,%5,%6,%7,%8,%9,%10,%11,%12,%13,%14,%15,"               \
        "%16,%17,%18,%19,%20,%21,%22,%23,%24,%25,%26,%27,%28,%29,%30,%31}, [%32];" \
        : "=r"((r)[0]),"=r"((r)[1]),"=r"((r)[2]),"=r"((r)[3]),                  \
          "=r"((r)[4]),"=r"((r)[5]),"=r"((r)[6]),"=r"((r)[7]),                  \
          "=r"((r)[8]),"=r"((r)[9]),"=r"((r)[10]),"=r"((r)[11]),                \
          "=r"((r)[12]),"=r"((r)[13]),"=r"((r)[14]),"=r"((r)[15]),              \
          "=r"((r)[16]),"=r"((r)[17]),"=r"((r)[18]),"=r"((r)[19]),              \
          "=r"((r)[20]),"=r"((r)[21]),"=r"((r)[22]),"=r"((r)[23]),              \
          "=r"((r)[24]),"=r"((r)[25]),"=r"((r)[26]),"=r"((r)[27]),              \
          "=r"((r)[28]),"=r"((r)[29]),"=r"((r)[30]),"=r"((r)[31])               \
        : "r"(a))

#define STTM_X32(a, r)                                                          \
    asm volatile("tcgen05.st.sync.aligned.32x32b.x32.b32 [%0], "                \
        "{%1,%2,%3,%4,%5,%6,%7,%8,%9,%10,%11,%12,%13,%14,%15,%16,"              \
        "%17,%18,%19,%20,%21,%22,%23,%24,%25,%26,%27,%28,%29,%30,%31,%32};"     \
        :: "r"(a),                                                              \
           "r"((r)[0]),"r"((r)[1]),"r"((r)[2]),"r"((r)[3]),                     \
           "r"((r)[4]),"r"((r)[5]),"r"((r)[6]),"r"((r)[7]),                     \
           "r"((r)[8]),"r"((r)[9]),"r"((r)[10]),"r"((r)[11]),                   \
           "r"((r)[12]),"r"((r)[13]),"r"((r)[14]),"r"((r)[15]),                 \
           "r"((r)[16]),"r"((r)[17]),"r"((r)[18]),"r"((r)[19]),                 \
           "r"((r)[20]),"r"((r)[21]),"r"((r)[22]),"r"((r)[23]),                 \
           "r"((r)[24]),"r"((r)[25]),"r"((r)[26]),"r"((r)[27]),                 \
           "r"((r)[28]),"r"((r)[29]),"r"((r)[30]),"r"((r)[31])                  \
        : "memory")
#endif // COMPILE_TC

// ---------------- prelude kernels ----------------
extern "C" __global__ void split_weights(const float* __restrict__ Wih,
                                         const float* __restrict__ Whh) {
    size_t tot4 = (size_t)NLAYER * HID * HID / 4;
    size_t i4 = (size_t)blockIdx.x * blockDim.x + threadIdx.x;
    if (i4 >= tot4) return;
    float4 a = __ldg((const float4*)Wih + i4);
    float4 b = __ldg((const float4*)Whh + i4);
    uint2 h, l;
    split2(a.x, a.y, h.x, l.x); split2(a.z, a.w, h.y, l.y);
    ((uint2*)g_w_hi)[i4] = h;  ((uint2*)g_w_lo)[i4] = l;
    split2(b.x, b.y, h.x, l.x); split2(b.z, b.w, h.y, l.y);
    ((uint2*)g_w_hi)[tot4 + i4] = h;  ((uint2*)g_w_lo)[tot4 + i4] = l;
}

extern "C" __global__ void split_x(const float* __restrict__ x) {
    size_t tot4 = Y_ELEMS / 4;
    for (size_t i4 = (size_t)blockIdx.x * blockDim.x + threadIdx.x;
         i4 < tot4; i4 += (size_t)gridDim.x * blockDim.x) {
        float4 a = __ldg((const float4*)x + i4);
        uint2 h, l;
        split2(a.x, a.y, h.x, l.x); split2(a.z, a.w, h.y, l.y);
        ((uint2*)g_x_hi)[i4] = h;  ((uint2*)g_x_lo)[i4] = l;
    }
}

// seed h0 into the parity slot read at t==0 for each layer: pp = (l+1)&1
extern "C" __global__ void seed_h0(const float* __restrict__ h0) {
    size_t tot4 = (size_t)NLAYER * BH / 4;
    size_t i4 = (size_t)blockIdx.x * blockDim.x + threadIdx.x;
    if (i4 >= tot4) return;
    int l = (int)(i4 / (BH / 4));
    size_t r4 = i4 % (BH / 4);
    int pp = (l + 1) & 1;
    float4 a = __ldg((const float4*)h0 + i4);
    uint2 h, lo;
    split2(a.x, a.y, h.x, lo.x); split2(a.z, a.w, h.y, lo.y);
    ((uint2*)&g_h_hi[pp][l][0][0])[r4] = h;
    ((uint2*)&g_h_lo[pp][l][0][0])[r4] = lo;
}

#if defined(COMPILE_TC)
// ---------------- A chunk load (single register set) ----------------
__device__ __forceinline__ void loadA(
    int ch, int tid,
    const __nv_bfloat16* a0h, const __nv_bfloat16* a0l,
    const __nv_bfloat16* a1h, const __nv_bfloat16* a1l,
    uint32_t* ah, uint32_t* al)
{
    const int g  = ch >> 4;
    const int k0 = (ch & 15) * KC;
    const size_t aoff = (size_t)tid * HID + k0;
    const uint4* sh = (const uint4*)((g ? a1h : a0h) + aoff);
    const uint4* sl = (const uint4*)((g ? a1l : a0l) + aoff);
    #pragma unroll
    for (int q = 0; q < 8; q++) {
        uint4 v = __ldcg(sh + q);
        ah[4*q] = v.x; ah[4*q+1] = v.y; ah[4*q+2] = v.z; ah[4*q+3] = v.w;
    }
    #pragma unroll
    for (int q = 0; q < 8; q++) {
        uint4 v = __ldcg(sl + q);
        al[4*q] = v.x; al[4*q+1] = v.y; al[4*q+2] = v.z; al[4*q+3] = v.w;
    }
}

// ---------------- W chunk fetch via cp.async (no registers) ----------------
__device__ __forceinline__ void cpW(int ch, int tid, int l, int n0, uint32_t wb) {
    const int g  = ch >> 4;
    const int k0 = (ch & 15) * KC;
    const int wrow = tid >> 2, qq = tid & 3;
    const size_t wbase = (((size_t)g * NLAYER + l) * HID + (n0 + wrow)) * HID + k0;
    #pragma unroll
    for (int e = 0; e < 2; e++) {
        int q = qq * 2 + e;
        uint32_t so = swz((uint32_t)wrow * 128u + (uint32_t)q * 16u);
        cp16(wb + so,           g_w_hi + wbase + q * 8);
        cp16(wb + OFF_WLO + so, g_w_lo + wbase + q * 8);
    }
}
#endif // COMPILE_TC

// ---------------- persistent RNN kernel ----------------
extern "C" __global__ void __launch_bounds__(NTHREADS, 1)
rnn_tc(const float* __restrict__ x,    // [S][B][H]
       const float* __restrict__ h0,   // [L][B][H]
       const float* __restrict__ Wih,  // fallback path only
       const float* __restrict__ Whh,  // fallback path only
       const float* __restrict__ bih,  // [L][H]
       const float* __restrict__ bhh,  // [L][H]
       float* __restrict__ out)        // y [S*B*H] ++ h_N [L*B*H]
{
#if defined(COMPILE_TC)
    // ================= tcgen05 TS-mode 3-pass path =================
    (void)x; (void)h0; (void)Wih; (void)Whh;
    extern __shared__ __align__(1024) char dynsm[];
    __shared__ __align__(16) uint64_t mbar[2];
    __shared__ uint32_t tmem_ptr_sm;
    __shared__ float bias_sm[NT];

    const int tid  = threadIdx.x;
    const int wid  = tid >> 5;
    const int lane = tid & 31;
    const int l    = blockIdx.x / TPL;
    const int n0   = (blockIdx.x % TPL) * NT;
    const uint32_t warp_off = (uint32_t)(wid & 3) << 21;  // TMEM subpartition
    const int half = tid >> 7;                            // M-half of my A row

    uint32_t smW = smem_u32(dynsm);
    smW = (smW + 1023u) & ~1023u;                         // W ring base
    const uint32_t mb0 = smem_u32(&mbar[0]);

    if (wid == 0) tc_alloc(smem_u32(&tmem_ptr_sm), 512);
    if (tid == 0) {
        MBARRIER_INIT(mb0 + 0, 1);
        MBARRIER_INIT(mb0 + 8, 1);
    }
    if (tid < NT)
        bias_sm[tid] = __ldg(&bih[l * HID + n0 + tid]) + __ldg(&bhh[l * HID + n0 + tid]);
    __syncthreads();
    const uint32_t tmem = tmem_ptr_sm;
    if (wid == 0) tc_relinquish();

    unsigned u0 = 0, u1 = 0;

    for (int s = 0; s < S_LEN + NLAYER - 1; s++) {
        if (s > 0) grid_barrier();
        const int t = s - l;
        if (t < 0 || t >= S_LEN) continue;
        const int pp = (s + 1) & 1;

        // A sources (all pre-split bf16)
        const __nv_bfloat16* a0h = (l == 0) ? (g_x_hi + (size_t)t * BH)
                                            : &g_h_hi[pp][l - 1][0][0];
        const __nv_bfloat16* a0l = (l == 0) ? (g_x_lo + (size_t)t * BH)
                                            : &g_h_lo[pp][l - 1][0][0];
        const __nv_bfloat16* a1h = &g_h_hi[pp][l][0][0];
        const __nv_bfloat16* a1l = &g_h_lo[pp][l][0][0];

        uint32_t ah[32], al[32];                // single A register set

        // prologue: A(0) into regs; W(0), W(1) in flight via cp.async
        loadA(0, tid, a0h, a0l, a1h, a1l, ah, al);
        cpW(0, tid, l, n0, smW + 0 * WBUFSZ); CP_COMMIT();
        cpW(1, tid, l, n0, smW + 1 * WBUFSZ); CP_COMMIT();

        #pragma unroll 1
        for (int ch = 0; ch < NCHUNK; ch++) {
            const int b = ch & 1;

            // free TMEM A slot b + W buf (ch+2)&3: MMAs of ch-2 must be done
            if (ch >= 2) {
                if (b == 0) { MBAR_WAIT(mb0 + 0, u0 & 1); u0++; }
                else        { MBAR_WAIT(mb0 + 8, u1 & 1); u1++; }
                TC_FENCE_AFTER();
            }
            // keep W pipeline 2 chunks ahead (dummy group at the tail keeps
            // the wait_group accounting exact)
            if (ch + 2 < NCHUNK)
                cpW(ch + 2, tid, l, n0, smW + (uint32_t)((ch + 2) & 3) * WBUFSZ);
            CP_COMMIT();

            // A(ch) -> TMEM slot b
            const uint32_t acol = tmem + TM_A + (uint32_t)b * 128u
                                + (uint32_t)half * 64u;
            STTM_X32(acol + warp_off, ah);
            STTM_X32(acol + 32u + warp_off, al);
            TC_WAIT_ST();                        // A regs now free

            // prefetch A(ch+1) into the freed registers (latency hides behind
            // the rest of this chunk + next chunk's front)
            if (ch + 1 < NCHUNK)
                loadA(ch + 1, tid, a0h, a0l, a1h, a1l, ah, al);

            CP_WAIT2();                          // W(ch) resident in SMEM
            TC_FENCE_BEFORE();                   // publish STTM to MMA
            FENCE_ASYNC();                       // publish cp.async W to MMA
            __syncthreads();

            if (tid == 0) {
                TC_FENCE_AFTER();
                const uint32_t wb = smW + (uint32_t)(ch & 3) * WBUFSZ;
                #pragma unroll
                for (int mh = 0; mh < 2; mh++) {
                    #pragma unroll
                    for (int ps = 0; ps < 3; ps++) {
                        // ps0: Ahi*Whi  ps1: Ahi*Wlo  ps2: Alo*Whi
                        uint32_t a0 = tmem + TM_A + (uint32_t)b * 128u
                                    + (uint32_t)mh * 64u + (ps == 2 ? 32u : 0u);
                        uint64_t bd = mkdesc(wb + (ps == 1 ? OFF_WLO : 0u));
                        #pragma unroll
                        for (int ks = 0; ks < 4; ks++) {
                            uint32_t en = !(ch == 0 && ps == 0 && ks == 0);
                            tc_mma_ts(tmem + TM_D + mh * 64, a0 + ks * 8,
                                      bd + ks * 2, IDESC, en);
                        }
                    }
                }
                tc_commit(b == 0 ? mb0 : mb0 + 8);
            }
        }

        // drain: each buffer has exactly one outstanding commit (chunks 30/31)
        MBAR_WAIT(mb0 + 0, u0 & 1); u0++;
        MBAR_WAIT(mb0 + 8, u1 & 1); u1++;
        TC_FENCE_AFTER();

        // ---- epilogue: LDTM -> +bias -> tanh -> split/store ----
        // Two 32-column halves to cap register pressure.
        {
            const int mh  = wid >> 2;
            const int row = mh * 128 + (wid & 3) * 32 + lane;
            const int wp  = s & 1;

            #pragma unroll
            for (int hf = 0; hf < 2; hf++) {
                uint32_t r[32];
                LDTM_X32(r, tmem + TM_D + mh * 64 + hf * 32);
                TC_WAIT_LD();

                float hv[32];
                #pragma unroll
                for (int c = 0; c < 32; c++)
                    hv[c] = tanhf(__uint_as_float(r[c]) + bias_sm[hf * 32 + c]);

                uint32_t hip[16], lop[16];
                #pragma unroll
                for (int c = 0; c < 32; c += 2)
                    split2(hv[c], hv[c + 1], hip[c >> 1], lop[c >> 1]);

                uint4* dh = (uint4*)&g_h_hi[wp][l][row][n0 + hf * 32];
                uint4* dl = (uint4*)&g_h_lo[wp][l][row][n0 + hf * 32];
                #pragma unroll
                for (int q = 0; q < 4; q++) {
                    dh[q] = make_uint4(hip[4*q], hip[4*q+1], hip[4*q+2], hip[4*q+3]);
                    dl[q] = make_uint4(lop[4*q], lop[4*q+1], lop[4*q+2], lop[4*q+3]);
                }
                if (l == NLAYER - 1) {
                    float4* yb = (float4*)(out + (size_t)t * BH
                                           + (size_t)row * HID + n0 + hf * 32);
                    #pragma unroll
                    for (int q = 0; q < 8; q++)
                        yb[q] = make_float4(hv[4*q], hv[4*q+1], hv[4*q+2], hv[4*q+3]);
                }
                if (t == S_LEN - 1) {
                    float4* hb = (float4*)(out + Y_ELEMS + (size_t)l * BH
                                           + (size_t)row * HID + n0 + hf * 32);
                    #pragma unroll
                    for (int q = 0; q < 8; q++)
                        hb[q] = make_float4(hv[4*q], hv[4*q+1], hv[4*q+2], hv[4*q+3]);
                }
            }
            TC_FENCE_BEFORE();
        }
    }

    __syncthreads();
    if (wid == 0) tc_dealloc(tmem, 512);

#else
    // ================= SIMT fp32x2 fallback (base sm_103 pass) =================
    extern __shared__ __align__(16) char dynsm[];
    float (*At)[FB_ASTR] = (float(*)[FB_ASTR])dynsm;
    float (*Wt)[FB_WSTR] = (float(*)[FB_WSTR])(dynsm + sizeof(float) * BATCH * FB_ASTR);

    const int tid = threadIdx.x;
    const int ty  = tid >> 2;
    const int tx  = tid & 3;
    const int l   = blockIdx.x / TPL;
    const int nb  = (blockIdx.x % TPL) * NT;

    const float* Wl_ih = Wih + (size_t)l * HID * HID;
    const float* Wl_hh = Whh + (size_t)l * HID * HID;

    for (int s = 0; s < S_LEN + NLAYER - 1; s++) {
        if (s > 0) grid_barrier();
        int t = s - l;
        if (t < 0 || t >= S_LEN) continue;

        const float* A0 = (l == 0) ? (x + (size_t)t * BH) : &g_hf[(s + 1) & 1][l - 1][0][0];
        const float* A1 = (t == 0) ? (h0 + (size_t)l * BH) : &g_hf[(s + 1) & 1][l][0][0];

        for (int st = 0; st < NT / 16; st++) {
            const int n0 = nb + st * 16;
            float bias[4];
            #pragma unroll
            for (int j = 0; j < 4; j++) {
                int c = n0 + tx * 4 + j;
                bias[j] = __ldg(&bih[l * HID + c]) + __ldg(&bhh[l * HID + c]);
            }
            unsigned long long acc[4][2];
            #pragma unroll
            for (int ri = 0; ri < 4; ri++) {
                acc[ri][0] = pack2(bias[0], bias[1]);
                acc[ri][1] = pack2(bias[2], bias[3]);
            }
            simt_gemm(A0, Wl_ih, n0, tid, ty, tx, acc, At, Wt);
            simt_gemm(A1, Wl_hh, n0, tid, ty, tx, acc, At, Wt);

            float* hb = &g_hf[s & 1][l][0][0];
            #pragma unroll
            for (int ri = 0; ri < 4; ri++) {
                float2 v0 = unpack2(acc[ri][0]);
                float2 v1 = unpack2(acc[ri][1]);
                float4 h;
                h.x = tanhf(v0.x); h.y = tanhf(v0.y);
                h.z = tanhf(v1.x); h.w = tanhf(v1.y);
                int row = ty + 64 * ri;
                size_t off = (size_t)row * HID + n0 + tx * 4;
                *(float4*)(hb + off) = h;
                if (l == NLAYER - 1)
                    *(float4*)(out + (size_t)t * BH + off) = h;
                if (t == S_LEN - 1)
                    *(float4*)(out + Y_ELEMS + (size_t)l * BH + off) = h;
            }
        }
    }
#endif
}

extern "C" void kernel_launch(void* const* d_in, const int* in_sizes, int n_in,
                              void* d_out, int out_size) {
    const float* x   = (const float*)d_in[0];
    const float* h0  = (const float*)d_in[1];
    const float* Wih = (const float*)d_in[2];
    const float* Whh = (const float*)d_in[3];
    const float* bih = (const float*)d_in[4];
    const float* bhh = (const float*)d_in[5];

    cudaFuncSetAttribute(rnn_tc, cudaFuncAttributeMaxDynamicSharedMemorySize, SMEM_DYN);

    size_t tot4 = (size_t)NLAYER * HID * HID / 4;
    split_weights<<<(unsigned)((tot4 + 255) / 256), 256>>>(Wih, Whh);
    split_x<<<4096, 256>>>(x);
    size_t h4 = (size_t)NLAYER * BH / 4;
    seed_h0<<<(unsigned)((h4 + 255) / 256), 256>>>(h0);
    rnn_tc<<<NCTA, NTHREADS, SMEM_DYN>>>(x, h0, Wih, Whh, bih, bhh, (float*)d_out);
}

// round 14
// speedup vs baseline: 1.9893x; 1.0488x over previous
#include <cuda_runtime.h>
#include <cuda_bf16.h>
#include <cstdint>
#include <cstddef>

// MinimalRNN 3-layer tanh RNN, S=256, B=256, H=1024.
// Persistent kernel, skewed layer pipeline (layer l computes t = s - l).
// sm_103a pass: tcgen05 bf16 3-pass (hi/lo split), TS mode (A in TMEM via
// STTM; W in SMEM via cp.async). Base sm_103 pass: SIMT fp32x2 fallback.
// R14: warp specialization — 8 stager warps + 1 dedicated MMA-issuer warp,
// per-chunk __syncthreads replaced by full/commit mbarrier pair so the
// stager control chain (fences, STTM, waits) pipelines against MMA issue.

#if defined(__CUDA_ARCH_FEAT_SM103_ALL) || defined(__CUDA_ARCH_FEAT_SM100_ALL) || \
    defined(__CUDA_ARCH_FEAT_SM101_ALL) || defined(__CUDA_ARCH_SPECIFIC__)
#define TC_OK 1
#endif
#if !defined(__CUDA_ARCH__) || defined(TC_OK)
#define COMPILE_TC 1          // host pass + arch-specific device pass
#endif

#define S_LEN   256
#define BATCH   256
#define HID     1024
#define NLAYER  3
#define NT      64
#define TPL     (HID / NT)          // 16
#define NCTA    (NLAYER * TPL)      // 48
#define NTHREADS 288                // 8 stager warps + 1 issuer warp
#define NSTAGER  256
#define KC      64                  // k elems per chunk
#define NCHUNK  32                  // 2 GEMMs x 16 chunks
#define BH      ((size_t)BATCH * HID)
#define Y_ELEMS ((size_t)S_LEN * BATCH * HID)

// W stage: 4-deep ring in SMEM, per buffer hi 8KB + lo 8KB
#define WBUFSZ  16384
#define OFF_WLO 8192
#define NWBUF   4
#define SMEM_DYN (NWBUF * WBUFSZ + 1024)

// TMEM columns: D at 0 (128 cols), A buffers at 128 (2 x 128 cols)
#define TM_D    0
#define TM_A    128

// idesc kind::f16: dtype=F32(1<<4) atype=BF16(1<<7) btype=BF16(1<<10)
// N/8=8 (<<17), M/16=8 (<<24)
#define IDESC 0x08100490u

// ---------------- global scratch ----------------
__device__ __align__(16) __nv_bfloat16 g_w_hi[2u * NLAYER * HID * HID];
__device__ __align__(16) __nv_bfloat16 g_w_lo[2u * NLAYER * HID * HID];
__device__ __align__(16) __nv_bfloat16 g_x_hi[(size_t)S_LEN * BATCH * HID];
__device__ __align__(16) __nv_bfloat16 g_x_lo[(size_t)S_LEN * BATCH * HID];
__device__ __align__(16) __nv_bfloat16 g_h_hi[2][NLAYER][BATCH][HID];
__device__ __align__(16) __nv_bfloat16 g_h_lo[2][NLAYER][BATCH][HID];
__device__ __align__(16) float         g_hf[2][NLAYER][BATCH][HID];  // fallback
__device__ unsigned g_count = 0;
__device__ unsigned g_gen   = 0;

// ---------------- generic helpers ----------------
__device__ __forceinline__ uint32_t smem_u32(const void* p) {
    uint32_t a;
    asm("{ .reg .u64 t; cvta.to.shared.u64 t, %1; cvt.u32.u64 %0, t; }"
        : "=r"(a) : "l"(p));
    return a;
}
__device__ __forceinline__ uint32_t swz(uint32_t off) {   // SW128
    return off ^ ((off >> 3) & 0x70);
}
__device__ __forceinline__ uint64_t mkdesc(uint32_t addr) { // SW128, LBO=1, SBO=64
    return ((uint64_t)2 << 61) | ((uint64_t)1 << 46) | ((uint64_t)64 << 32)
         | ((uint64_t)1 << 16) | ((addr >> 4) & 0x3FFF);
}
__device__ __forceinline__ uint32_t pkbf(__nv_bfloat16 a, __nv_bfloat16 b) {
    __nv_bfloat162 t = __halves2bfloat162(a, b);
    return *reinterpret_cast<uint32_t*>(&t);
}
__device__ __forceinline__ void split2(float x, float y, uint32_t& h, uint32_t& l) {
    __nv_bfloat16 hx = __float2bfloat16(x), hy = __float2bfloat16(y);
    __nv_bfloat16 lx = __float2bfloat16(x - __bfloat162float(hx));
    __nv_bfloat16 ly = __float2bfloat16(y - __bfloat162float(hy));
    h = pkbf(hx, hy); l = pkbf(lx, ly);
}

// ---------------- grid barrier ----------------
__device__ __forceinline__ unsigned ld_acq(const unsigned* p) {
    unsigned v;
    asm volatile("ld.acquire.gpu.global.u32 %0, [%1];" : "=r"(v) : "l"(p) : "memory");
    return v;
}
__device__ __forceinline__ void grid_barrier() {
    __syncthreads();
    if (threadIdx.x == 0) {
        __threadfence();
        unsigned gen = ld_acq(&g_gen);
        __threadfence();
        unsigned ticket = atomicAdd(&g_count, 1u);
        if (ticket == NCTA - 1) {
            atomicExch(&g_count, 0u);
            __threadfence();
            atomicAdd(&g_gen, 1u);
        } else {
            while (ld_acq(&g_gen) == gen) { __nanosleep(64); }
        }
        __threadfence();
    }
    __syncthreads();
}

// ---------------- packed f32x2 (fallback path) ----------------
__device__ __forceinline__ void ffma2(unsigned long long& d,
                                      unsigned long long a, unsigned long long b) {
    asm volatile("fma.rn.f32x2 %0, %1, %2, %0;" : "+l"(d) : "l"(a), "l"(b));
}
__device__ __forceinline__ unsigned long long splat2(float v) {
    unsigned long long r;
    asm("mov.b64 %0, {%1, %1};" : "=l"(r) : "f"(v));
    return r;
}
__device__ __forceinline__ unsigned long long pack2(float a, float b) {
    unsigned long long r;
    asm("mov.b64 %0, {%1, %2};" : "=l"(r) : "f"(a), "f"(b));
    return r;
}
__device__ __forceinline__ float2 unpack2(unsigned long long v) {
    float2 f;
    asm("mov.b64 {%0, %1}, %2;" : "=f"(f.x), "=f"(f.y) : "l"(v));
    return f;
}

#define FB_KC   32
#define FB_ASTR 36
#define FB_WSTR 20
__device__ __forceinline__ void simt_gemm(
    const float* __restrict__ A, const float* __restrict__ W,
    int n0, int tid, int ty, int tx,
    unsigned long long acc[4][2],
    float (*At)[FB_ASTR], float (*Wt)[FB_WSTR])
{
    const int arow = tid >> 3, aq = tid & 7;
    const int wc = tid & 15, wq = tid >> 4;
    for (int kc = 0; kc < HID; kc += FB_KC) {
        if (tid < 256) {
            #pragma unroll
            for (int it = 0; it < 8; it++) {
                int row = arow + 32 * it;
                float4 v = __ldcg((const float4*)(A + (size_t)row * HID + kc + aq * 4));
                *(float4*)&At[row][aq * 4] = v;
            }
        }
        if (tid < 128) {
            float4 wv = __ldg((const float4*)(W + (size_t)(n0 + wc) * HID + kc + wq * 4));
            Wt[wq * 4 + 0][wc] = wv.x; Wt[wq * 4 + 1][wc] = wv.y;
            Wt[wq * 4 + 2][wc] = wv.z; Wt[wq * 4 + 3][wc] = wv.w;
        }
        __syncthreads();
        if (tid < 256) {
            #pragma unroll
            for (int k4 = 0; k4 < FB_KC; k4 += 4) {
                ulonglong2 wp[4];
                #pragma unroll
                for (int j = 0; j < 4; j++)
                    wp[j] = *(const ulonglong2*)&Wt[k4 + j][tx * 4];
                float4 av[4];
                #pragma unroll
                for (int ri = 0; ri < 4; ri++)
                    av[ri] = *(const float4*)&At[ty + 64 * ri][k4];
                #pragma unroll
                for (int j = 0; j < 4; j++) {
                    #pragma unroll
                    for (int ri = 0; ri < 4; ri++) {
                        unsigned long long as = splat2(((const float*)&av[ri])[j]);
                        ffma2(acc[ri][0], as, wp[j].x);
                        ffma2(acc[ri][1], as, wp[j].y);
                    }
                }
            }
        }
        __syncthreads();
    }
}

// ---------------- tcgen05 / async wrappers (arch-specific pass only) --------
#if defined(COMPILE_TC)
#define MBARRIER_INIT(addr, cnt) \
    asm volatile("mbarrier.init.shared.b64 [%0], %1;" :: "r"(addr), "r"(cnt) : "memory")
#define MBAR_ARRIVE(addr) \
    asm volatile("mbarrier.arrive.shared.b64 _, [%0];" :: "r"(addr) : "memory")
#define MBAR_WAIT(addr, parity) do {                                            \
    uint32_t _done;                                                             \
    asm volatile("{\n\t.reg .pred p;\n\t"                                       \
        "mbarrier.try_wait.parity.acquire.cta.shared::cta.b64 p, [%1], %2;\n\t" \
        "selp.b32 %0, 1, 0, p;\n\t}"                                            \
        : "=r"(_done) : "r"(addr), "r"(parity) : "memory");                     \
    if (!_done) {                                                               \
        asm volatile("{\n\t.reg .pred P1;\n\t"                                  \
            "WL_%=:\n\t"                                                        \
            "mbarrier.try_wait.parity.acquire.cta.shared::cta.b64 P1, [%0], %1, 0x989680;\n\t" \
            "@P1 bra.uni WD_%=;\n\t"                                            \
            "bra.uni WL_%=;\n\t"                                                \
            "WD_%=:\n\t}" :: "r"(addr), "r"(parity) : "memory");                \
    }                                                                           \
} while (0)

__device__ __forceinline__ void tc_alloc(uint32_t dst_smem, uint32_t ncols) {
    asm volatile("tcgen05.alloc.cta_group::1.sync.aligned.shared::cta.b32 [%0], %1;"
                 :: "r"(dst_smem), "r"(ncols) : "memory");
}
__device__ __forceinline__ void tc_dealloc(uint32_t tmem, uint32_t ncols) {
    asm volatile("tcgen05.dealloc.cta_group::1.sync.aligned.b32 %0, %1;"
                 :: "r"(tmem), "r"(ncols));
}
__device__ __forceinline__ void tc_relinquish() {
    asm volatile("tcgen05.relinquish_alloc_permit.cta_group::1.sync.aligned;");
}
// TS form: A operand in TMEM
__device__ __forceinline__ void tc_mma_ts(uint32_t d, uint32_t a, uint64_t bd,
                                          uint32_t idesc, uint32_t en) {
    asm volatile("{\n\t.reg .pred p;\n\tsetp.ne.u32 p, %5, 0;\n\t"
        "tcgen05.mma.cta_group::1.kind::f16 [%0], [%1], %2, %3, {%4,%4,%4,%4}, p;\n\t}"
        :: "r"(d), "r"(a), "l"(bd), "r"(idesc), "r"(0u), "r"(en) : "memory");
}
__device__ __forceinline__ void tc_commit(uint32_t mbar) {
    asm volatile("tcgen05.commit.cta_group::1.mbarrier::arrive::one.shared::cluster.b64 [%0];"
                 :: "r"(mbar) : "memory");
}
#define TC_FENCE_BEFORE() asm volatile("tcgen05.fence::before_thread_sync;" ::: "memory")
#define TC_FENCE_AFTER()  asm volatile("tcgen05.fence::after_thread_sync;"  ::: "memory")
#define TC_WAIT_LD()      asm volatile("tcgen05.wait::ld.sync.aligned;" ::: "memory")
#define TC_WAIT_ST()      asm volatile("tcgen05.wait::st.sync.aligned;" ::: "memory")
#define FENCE_ASYNC()     asm volatile("fence.proxy.async.shared::cta;" ::: "memory")

// cp.async 16B global->shared (LDGSTS), bypasses registers
__device__ __forceinline__ void cp16(uint32_t dst, const void* src) {
    asm volatile("cp.async.cg.shared.global [%0], [%1], 16;"
                 :: "r"(dst), "l"(src) : "memory");
}
#define CP_COMMIT() asm volatile("cp.async.commit_group;" ::: "memory")
#define CP_WAIT2()  asm volatile("cp.async.wait_group 2;" ::: "memory")

#define LDTM_X32(r, a)                                                          \
    asm volatile("tcgen05.ld.sync.aligned.32x32b.x32.b32 "                      \
        "{%0,%1,%2,%3,%4,%5,%6,%7,%8,%9,%10,%11,%12,%13,%14,%15,"               \
        "%16,%17,%18,%19,%20,%21,%22,%23,%24,%25,%26,%27,%28,%29,%30,%31}, [%32];" \
        : "=r"((r)[0]),"=r"((r)[1]),"=r"((r)[2]),"=r"((r)[3]),                  \
          "=r"((r)[4]),"=r"((r)[5]),"=r"((r)[6]),"=r"((r)[7]),                  \
          "=r"((r)[8]),"=r"((r)[9]),"=r"((r)[10]),"=r"((r)[11]),                \
          "=r"((r)[12]),"=r"((r)[13]),"=r"((r)[14]),"=r"((r)[15]),              \
          "=r"((r)[16]),"=r"((r)[17]),"=r"((r)[18]),"=r"((r)[19]),              \
          "=r"((r)[20]),"=r"((r)[21]),"=r"((r)[22]),"=r"((r)[23]),              \
          "=r"((r)[24]),"=r"((r)[25]),"=r"((r)[26]),"=r"((r)[27]),              \
          "=r"((r)[28]),"=r"((r)[29]),"=r"((r)[30]),"=r"((r)[31])               \
        : "r"(a))

#define STTM_X32(a, r)                                                          \
    asm volatile("tcgen05.st.sync.aligned.32x32b.x32.b32 [%0], "                \
        "{%1,%2,%3,%4,%5,%6,%7,%8,%9,%10,%11,%12,%13,%14,%15,%16,"              \
        "%17,%18,%19,%20,%21,%22,%23,%24,%25,%26,%27,%28,%29,%30,%31,%32};"     \
        :: "r"(a),                                                              \
           "r"((r)[0]),"r"((r)[1]),"r"((r)[2]),"r"((r)[3]),                     \
           "r"((r)[4]),"r"((r)[5]),"r"((r)[6]),"r"((r)[7]),                     \
           "r"((r)[8]),"r"((r)[9]),"r"((r)[10]),"r"((r)[11]),                   \
           "r"((r)[12]),"r"((r)[13]),"r"((r)[14]),"r"((r)[15]),                 \
           "r"((r)[16]),"r"((r)[17]),"r"((r)[18]),"r"((r)[19]),                 \
           "r"((r)[20]),"r"((r)[21]),"r"((r)[22]),"r"((r)[23]),                 \
           "r"((r)[24]),"r"((r)[25]),"r"((r)[26]),"r"((r)[27]),                 \
           "r"((r)[28]),"r"((r)[29]),"r"((r)[30]),"r"((r)[31])                  \
        : "memory")
#endif // COMPILE_TC

// ---------------- prelude kernels ----------------
extern "C" __global__ void split_weights(const float* __restrict__ Wih,
                                         const float* __restrict__ Whh) {
    size_t tot4 = (size_t)NLAYER * HID * HID / 4;
    size_t i4 = (size_t)blockIdx.x * blockDim.x + threadIdx.x;
    if (i4 >= tot4) return;
    float4 a = __ldg((const float4*)Wih + i4);
    float4 b = __ldg((const float4*)Whh + i4);
    uint2 h, l;
    split2(a.x, a.y, h.x, l.x); split2(a.z, a.w, h.y, l.y);
    ((uint2*)g_w_hi)[i4] = h;  ((uint2*)g_w_lo)[i4] = l;
    split2(b.x, b.y, h.x, l.x); split2(b.z, b.w, h.y, l.y);
    ((uint2*)g_w_hi)[tot4 + i4] = h;  ((uint2*)g_w_lo)[tot4 + i4] = l;
}

extern "C" __global__ void split_x(const float* __restrict__ x) {
    size_t tot4 = Y_ELEMS / 4;
    for (size_t i4 = (size_t)blockIdx.x * blockDim.x + threadIdx.x;
         i4 < tot4; i4 += (size_t)gridDim.x * blockDim.x) {
        float4 a = __ldg((const float4*)x + i4);
        uint2 h, l;
        split2(a.x, a.y, h.x, l.x); split2(a.z, a.w, h.y, l.y);
        ((uint2*)g_x_hi)[i4] = h;  ((uint2*)g_x_lo)[i4] = l;
    }
}

// seed h0 into the parity slot read at t==0 for each layer: pp = (l+1)&1
extern "C" __global__ void seed_h0(const float* __restrict__ h0) {
    size_t tot4 = (size_t)NLAYER * BH / 4;
    size_t i4 = (size_t)blockIdx.x * blockDim.x + threadIdx.x;
    if (i4 >= tot4) return;
    int l = (int)(i4 / (BH / 4));
    size_t r4 = i4 % (BH / 4);
    int pp = (l + 1) & 1;
    float4 a = __ldg((const float4*)h0 + i4);
    uint2 h, lo;
    split2(a.x, a.y, h.x, lo.x); split2(a.z, a.w, h.y, lo.y);
    ((uint2*)&g_h_hi[pp][l][0][0])[r4] = h;
    ((uint2*)&g_h_lo[pp][l][0][0])[r4] = lo;
}

#if defined(COMPILE_TC)
// ---------------- A chunk load (single register set, stager threads) -------
__device__ __forceinline__ void loadA(
    int ch, int tid,
    const __nv_bfloat16* a0h, const __nv_bfloat16* a0l,
    const __nv_bfloat16* a1h, const __nv_bfloat16* a1l,
    uint32_t* ah, uint32_t* al)
{
    const int g  = ch >> 4;
    const int k0 = (ch & 15) * KC;
    const size_t aoff = (size_t)tid * HID + k0;
    const uint4* sh = (const uint4*)((g ? a1h : a0h) + aoff);
    const uint4* sl = (const uint4*)((g ? a1l : a0l) + aoff);
    #pragma unroll
    for (int q = 0; q < 8; q++) {
        uint4 v = __ldcg(sh + q);
        ah[4*q] = v.x; ah[4*q+1] = v.y; ah[4*q+2] = v.z; ah[4*q+3] = v.w;
    }
    #pragma unroll
    for (int q = 0; q < 8; q++) {
        uint4 v = __ldcg(sl + q);
        al[4*q] = v.x; al[4*q+1] = v.y; al[4*q+2] = v.z; al[4*q+3] = v.w;
    }
}

// ---------------- W chunk fetch via cp.async (stager threads) --------------
__device__ __forceinline__ void cpW(int ch, int tid, int l, int n0, uint32_t wb) {
    const int g  = ch >> 4;
    const int k0 = (ch & 15) * KC;
    const int wrow = tid >> 2, qq = tid & 3;
    const size_t wbase = (((size_t)g * NLAYER + l) * HID + (n0 + wrow)) * HID + k0;
    #pragma unroll
    for (int e = 0; e < 2; e++) {
        int q = qq * 2 + e;
        uint32_t so = swz((uint32_t)wrow * 128u + (uint32_t)q * 16u);
        cp16(wb + so,           g_w_hi + wbase + q * 8);
        cp16(wb + OFF_WLO + so, g_w_lo + wbase + q * 8);
    }
}
#endif // COMPILE_TC

// ---------------- persistent RNN kernel ----------------
extern "C" __global__ void __launch_bounds__(NTHREADS, 1)
rnn_tc(const float* __restrict__ x,    // [S][B][H]
       const float* __restrict__ h0,   // [L][B][H]
       const float* __restrict__ Wih,  // fallback path only
       const float* __restrict__ Whh,  // fallback path only
       const float* __restrict__ bih,  // [L][H]
       const float* __restrict__ bhh,  // [L][H]
       float* __restrict__ out)        // y [S*B*H] ++ h_N [L*B*H]
{
#if defined(COMPILE_TC)
    // ================= tcgen05 warp-specialized path =================
    (void)x; (void)h0; (void)Wih; (void)Whh;
    extern __shared__ __align__(1024) char dynsm[];
    __shared__ __align__(16) uint64_t cmbar[2];   // commit (MMA done) per slot
    __shared__ __align__(16) uint64_t fmbar[2];   // full (staged) per slot
    __shared__ uint32_t tmem_ptr_sm;
    __shared__ float bias_sm[NT];

    const int tid  = threadIdx.x;
    const int wid  = tid >> 5;
    const int lane = tid & 31;
    const int l    = blockIdx.x / TPL;
    const int n0   = (blockIdx.x % TPL) * NT;
    const bool issuer = (wid == 8);
    const uint32_t warp_off = (uint32_t)(wid & 3) << 21;  // TMEM subpartition
    const int half = (tid >> 7) & 1;                      // M-half of my A row

    uint32_t smW = smem_u32(dynsm);
    smW = (smW + 1023u) & ~1023u;                         // W ring base
    const uint32_t cm0 = smem_u32(&cmbar[0]);
    const uint32_t fm0 = smem_u32(&fmbar[0]);

    if (wid == 0) tc_alloc(smem_u32(&tmem_ptr_sm), 512);
    if (tid == 0) {
        MBARRIER_INIT(cm0 + 0, 1);  MBARRIER_INIT(cm0 + 8, 1);
        MBARRIER_INIT(fm0 + 0, 8);  MBARRIER_INIT(fm0 + 8, 8);
    }
    if (tid < NT)
        bias_sm[tid] = __ldg(&bih[l * HID + n0 + tid]) + __ldg(&bhh[l * HID + n0 + tid]);
    __syncthreads();
    const uint32_t tmem = tmem_ptr_sm;
    if (wid == 0) tc_relinquish();

    unsigned c0 = 0, c1 = 0;       // commit-mbar parity counters (stagers)
    unsigned f0 = 0, f1 = 0;       // full-mbar parity counters (issuer)

    for (int s = 0; s < S_LEN + NLAYER - 1; s++) {
        if (s > 0) grid_barrier();
        const int t = s - l;
        if (t < 0 || t >= S_LEN) continue;
        const int pp = (s + 1) & 1;

        const __nv_bfloat16* a0h = (l == 0) ? (g_x_hi + (size_t)t * BH)
                                            : &g_h_hi[pp][l - 1][0][0];
        const __nv_bfloat16* a0l = (l == 0) ? (g_x_lo + (size_t)t * BH)
                                            : &g_h_lo[pp][l - 1][0][0];
        const __nv_bfloat16* a1h = &g_h_hi[pp][l][0][0];
        const __nv_bfloat16* a1l = &g_h_lo[pp][l][0][0];

        if (!issuer) {
            // ================== STAGER WARPS (0-7) ==================
            uint32_t ah[32], al[32];
            loadA(0, tid, a0h, a0l, a1h, a1l, ah, al);
            cpW(0, tid, l, n0, smW + 0 * WBUFSZ); CP_COMMIT();
            cpW(1, tid, l, n0, smW + 1 * WBUFSZ); CP_COMMIT();

            #pragma unroll 1
            for (int ch = 0; ch < NCHUNK; ch++) {
                const int b = ch & 1;
                // slot b free when MMAs of ch-2 committed
                if (ch >= 2) {
                    if (b == 0) { MBAR_WAIT(cm0 + 0, c0 & 1); c0++; }
                    else        { MBAR_WAIT(cm0 + 8, c1 & 1); c1++; }
                    TC_FENCE_AFTER();
                }
                if (ch + 2 < NCHUNK)
                    cpW(ch + 2, tid, l, n0, smW + (uint32_t)((ch + 2) & 3) * WBUFSZ);
                CP_COMMIT();

                const uint32_t acol = tmem + TM_A + (uint32_t)b * 128u
                                    + (uint32_t)half * 64u;
                STTM_X32(acol + warp_off, ah);
                STTM_X32(acol + 32u + warp_off, al);
                TC_WAIT_ST();

                if (ch + 1 < NCHUNK)
                    loadA(ch + 1, tid, a0h, a0l, a1h, a1l, ah, al);

                CP_WAIT2();                      // W(ch) resident
                TC_FENCE_BEFORE();               // publish STTM
                FENCE_ASYNC();                   // publish cp.async W
                if (lane == 0)
                    MBAR_ARRIVE(b == 0 ? fm0 : fm0 + 8);
            }
            // drain: last commit per slot (chunks 30/31)
            MBAR_WAIT(cm0 + 0, c0 & 1); c0++;
            MBAR_WAIT(cm0 + 8, c1 & 1); c1++;
            TC_FENCE_AFTER();
        } else {
            // ================== ISSUER WARP (8) ==================
            #pragma unroll 1
            for (int ch = 0; ch < NCHUNK; ch++) {
                const int b = ch & 1;
                if (b == 0) { MBAR_WAIT(fm0 + 0, f0 & 1); f0++; }
                else        { MBAR_WAIT(fm0 + 8, f1 & 1); f1++; }
                TC_FENCE_AFTER();
                if (lane == 0) {
                    const uint32_t wb = smW + (uint32_t)(ch & 3) * WBUFSZ;
                    #pragma unroll
                    for (int mh = 0; mh < 2; mh++) {
                        #pragma unroll
                        for (int ps = 0; ps < 3; ps++) {
                            // ps0: Ahi*Whi  ps1: Ahi*Wlo  ps2: Alo*Whi
                            uint32_t a0 = tmem + TM_A + (uint32_t)b * 128u
                                        + (uint32_t)mh * 64u + (ps == 2 ? 32u : 0u);
                            uint64_t bd = mkdesc(wb + (ps == 1 ? OFF_WLO : 0u));
                            #pragma unroll
                            for (int ks = 0; ks < 4; ks++) {
                                uint32_t en = !(ch == 0 && ps == 0 && ks == 0);
                                tc_mma_ts(tmem + TM_D + mh * 64, a0 + ks * 8,
                                          bd + ks * 2, IDESC, en);
                            }
                        }
                    }
                    tc_commit(b == 0 ? cm0 : cm0 + 8);
                }
            }
        }

        // ---- epilogue (stager warps only): LDTM -> +bias -> tanh -> store ----
        if (!issuer) {
            const int mh  = wid >> 2;
            const int row = mh * 128 + (wid & 3) * 32 + lane;
            const int wp  = s & 1;

            #pragma unroll
            for (int hf = 0; hf < 2; hf++) {
                uint32_t r[32];
                LDTM_X32(r, tmem + TM_D + mh * 64 + hf * 32);
                TC_WAIT_LD();

                float hv[32];
                #pragma unroll
                for (int c = 0; c < 32; c++)
                    hv[c] = tanhf(__uint_as_float(r[c]) + bias_sm[hf * 32 + c]);

                uint32_t hip[16], lop[16];
                #pragma unroll
                for (int c = 0; c < 32; c += 2)
                    split2(hv[c], hv[c + 1], hip[c >> 1], lop[c >> 1]);

                uint4* dh = (uint4*)&g_h_hi[wp][l][row][n0 + hf * 32];
                uint4* dl = (uint4*)&g_h_lo[wp][l][row][n0 + hf * 32];
                #pragma unroll
                for (int q = 0; q < 4; q++) {
                    dh[q] = make_uint4(hip[4*q], hip[4*q+1], hip[4*q+2], hip[4*q+3]);
                    dl[q] = make_uint4(lop[4*q], lop[4*q+1], lop[4*q+2], lop[4*q+3]);
                }
                if (l == NLAYER - 1) {
                    float4* yb = (float4*)(out + (size_t)t * BH
                                           + (size_t)row * HID + n0 + hf * 32);
                    #pragma unroll
                    for (int q = 0; q < 8; q++)
                        yb[q] = make_float4(hv[4*q], hv[4*q+1], hv[4*q+2], hv[4*q+3]);
                }
                if (t == S_LEN - 1) {
                    float4* hb = (float4*)(out + Y_ELEMS + (size_t)l * BH
                                           + (size_t)row * HID + n0 + hf * 32);
                    #pragma unroll
                    for (int q = 0; q < 8; q++)
                        hb[q] = make_float4(hv[4*q], hv[4*q+1], hv[4*q+2], hv[4*q+3]);
                }
            }
            TC_FENCE_BEFORE();
        }
    }

    __syncthreads();
    if (wid == 0) tc_dealloc(tmem, 512);

#else
    // ================= SIMT fp32x2 fallback (base sm_103 pass) =================
    extern __shared__ __align__(16) char dynsm[];
    float (*At)[FB_ASTR] = (float(*)[FB_ASTR])dynsm;
    float (*Wt)[FB_WSTR] = (float(*)[FB_WSTR])(dynsm + sizeof(float) * BATCH * FB_ASTR);

    const int tid = threadIdx.x;
    const int ty  = tid >> 2;
    const int tx  = tid & 3;
    const int l   = blockIdx.x / TPL;
    const int nb  = (blockIdx.x % TPL) * NT;

    const float* Wl_ih = Wih + (size_t)l * HID * HID;
    const float* Wl_hh = Whh + (size_t)l * HID * HID;

    for (int s = 0; s < S_LEN + NLAYER - 1; s++) {
        if (s > 0) grid_barrier();
        int t = s - l;
        if (t < 0 || t >= S_LEN) continue;

        const float* A0 = (l == 0) ? (x + (size_t)t * BH) : &g_hf[(s + 1) & 1][l - 1][0][0];
        const float* A1 = (t == 0) ? (h0 + (size_t)l * BH) : &g_hf[(s + 1) & 1][l][0][0];

        for (int st = 0; st < NT / 16; st++) {
            const int n0 = nb + st * 16;
            float bias[4];
            #pragma unroll
            for (int j = 0; j < 4; j++) {
                int c = n0 + tx * 4 + j;
                bias[j] = __ldg(&bih[l * HID + c]) + __ldg(&bhh[l * HID + c]);
            }
            unsigned long long acc[4][2];
            #pragma unroll
            for (int ri = 0; ri < 4; ri++) {
                acc[ri][0] = pack2(bias[0], bias[1]);
                acc[ri][1] = pack2(bias[2], bias[3]);
            }
            simt_gemm(A0, Wl_ih, n0, tid, ty, tx, acc, At, Wt);
            simt_gemm(A1, Wl_hh, n0, tid, ty, tx, acc, At, Wt);

            if (tid < 256) {
                float* hb = &g_hf[s & 1][l][0][0];
                #pragma unroll
                for (int ri = 0; ri < 4; ri++) {
                    float2 v0 = unpack2(acc[ri][0]);
                    float2 v1 = unpack2(acc[ri][1]);
                    float4 h;
                    h.x = tanhf(v0.x); h.y = tanhf(v0.y);
                    h.z = tanhf(v1.x); h.w = tanhf(v1.y);
                    int row = ty + 64 * ri;
                    size_t off = (size_t)row * HID + n0 + tx * 4;
                    *(float4*)(hb + off) = h;
                    if (l == NLAYER - 1)
                        *(float4*)(out + (size_t)t * BH + off) = h;
                    if (t == S_LEN - 1)
                        *(float4*)(out + Y_ELEMS + (size_t)l * BH + off) = h;
                }
            }
        }
    }
#endif
}

extern "C" void kernel_launch(void* const* d_in, const int* in_sizes, int n_in,
                              void* d_out, int out_size) {
    const float* x   = (const float*)d_in[0];
    const float* h0  = (const float*)d_in[1];
    const float* Wih = (const float*)d_in[2];
    const float* Whh = (const float*)d_in[3];
    const float* bih = (const float*)d_in[4];
    const float* bhh = (const float*)d_in[5];

    cudaFuncSetAttribute(rnn_tc, cudaFuncAttributeMaxDynamicSharedMemorySize, SMEM_DYN);

    size_t tot4 = (size_t)NLAYER * HID * HID / 4;
    split_weights<<<(unsigned)((tot4 + 255) / 256), 256>>>(Wih, Whh);
    split_x<<<4096, 256>>>(x);
    size_t h4 = (size_t)NLAYER * BH / 4;
    seed_h0<<<(unsigned)((h4 + 255) / 256), 256>>>(h0);
    rnn_tc<<<NCTA, NTHREADS, SMEM_DYN>>>(x, h0, Wih, Whh, bih, bhh, (float*)d_out);
}